// round 2
// baseline (speedup 1.0000x reference)
#include <cuda_runtime.h>
#include <math.h>
#include <stdint.h>

// Problem constants
#define BATCH 4
#define SEQ   2048
#define EMB   1024
#define HEADS 16
#define HD    64
#define NTOK  (BATCH*SEQ)     // 8192
#define BH    (BATCH*HEADS)   // 64
#define NQUBITS 6

// ---------------- scratch (static device globals; no allocation) ----------------
__device__ float g_Q[BH*SEQ*HD];       // (b,h,s,d)
__device__ float g_K[BH*SEQ*HD];
__device__ float g_V[BH*SEQ*HD];
__device__ float g_O[NTOK*EMB];        // (b,s,e)
__device__ float g_Wq[EMB*EMB];        // effective Q projection weight
__device__ float g_Wk[EMB*EMB];
__device__ float g_Mq[HD*HD];
__device__ float g_Mk[HD*HD];
__device__ float g_beq[HD];
__device__ float g_bek[HD];
__device__ float g_bqf[EMB];
__device__ float g_bkf[EMB];

// ---------------- quantum layer composition ----------------
// Meff = postW @ R @ preW + I ; beff = postW @ R @ preb + postb
// R = product of 6 butterfly rotation stages acting on the 64 features.
__global__ __launch_bounds__(256) void quantum_compose(
    const float* __restrict__ theta, const float* __restrict__ phi,
    const float* __restrict__ preW, const float* __restrict__ preb,
    const float* __restrict__ postW, const float* __restrict__ postb,
    float* __restrict__ Meff, float* __restrict__ beff)
{
    __shared__ float A[HD][HD+1];
    __shared__ float bv[HD];
    int t = threadIdx.x;
    for (int idx = t; idx < HD*HD; idx += 256) A[idx >> 6][idx & 63] = preW[idx];
    if (t < HD) bv[t] = preb[t];
    __syncthreads();
    for (int i = 0; i < NQUBITS; i++) {
        float th = theta[i], ph = phi[i];
        float c = cosf(th), s = sinf(th), cp = cosf(ph);
        // 32 pairs x 64 cols
        for (int w = t; w < 32*HD; w += 256) {
            int p = w >> 6, col = w & 63;
            int low = p & ((1 << i) - 1);
            int i0 = ((p >> i) << (i + 1)) | low;
            int i1 = i0 | (1 << i);
            float x0 = A[i0][col], x1 = A[i1][col];
            A[i0][col] = c * x0 - s * x1;
            A[i1][col] = cp * (s * x0 + c * x1);
        }
        if (t < 32) {
            int p = t;
            int low = p & ((1 << i) - 1);
            int i0 = ((p >> i) << (i + 1)) | low;
            int i1 = i0 | (1 << i);
            float x0 = bv[i0], x1 = bv[i1];
            bv[i0] = c * x0 - s * x1;
            bv[i1] = cp * (s * x0 + c * x1);
        }
        __syncthreads();
    }
    // Meff[i][j] = sum_d postW[i,d]*A[d][j] + (i==j)
    for (int idx = t; idx < HD*HD; idx += 256) {
        int i = idx >> 6, j = idx & 63;
        float acc = (i == j) ? 1.0f : 0.0f;
        #pragma unroll 8
        for (int d = 0; d < HD; d++) acc += postW[i*HD + d] * A[d][j];
        Meff[idx] = acc;
    }
    if (t < HD) {
        float acc = postb[t];
        #pragma unroll 8
        for (int d = 0; d < HD; d++) acc += postW[t*HD + d] * bv[d];
        beff[t] = acc;
    }
}

// weff[h*64+i][j] = sum_d Meff[i][d] * w[h*64+d][j]
__global__ __launch_bounds__(256) void make_weff(
    const float* __restrict__ M, const float* __restrict__ w, float* __restrict__ weff)
{
    int r = blockIdx.y;
    int j = blockIdx.x * 256 + threadIdx.x;
    int h = r >> 6, i = r & 63;
    __shared__ float Mrow[HD];
    if (threadIdx.x < HD) Mrow[threadIdx.x] = M[i*HD + threadIdx.x];
    __syncthreads();
    float acc = 0.0f;
    #pragma unroll 8
    for (int d = 0; d < HD; d++) acc += Mrow[d] * w[(h*HD + d) * EMB + j];
    weff[(size_t)r * EMB + j] = acc;
}

// bfull[h*64+i] = beff[i] + sum_d Meff[i][d]*b_in[h*64+d]
__global__ __launch_bounds__(256) void make_beff(
    const float* __restrict__ M, const float* __restrict__ beff,
    const float* __restrict__ b_in, float* __restrict__ bfull)
{
    int r = blockIdx.x * 256 + threadIdx.x;
    int h = r >> 6, i = r & 63;
    float acc = beff[i];
    #pragma unroll 8
    for (int d = 0; d < HD; d++) acc += M[i*HD + d] * b_in[h*HD + d];
    bfull[r] = acc;
}

// ---------------- big GEMM: C = X(8192x1024) @ W^T(1024x1024) + bias ----------------
// BM=BN=128, BK=16, 256 threads, 8x8 microtile.
// qkvLayout: scatter output into (b,h,s,d); else flat (m,n).
#define BM 128
#define BN 128
#define BK 16
__global__ __launch_bounds__(256) void sgemm_kernel(
    const float* __restrict__ X, const float* __restrict__ W,
    const float* __restrict__ bias, float* __restrict__ out, int qkvLayout)
{
    __shared__ float As[BK][BM+1];
    __shared__ float Bs[BK][BN+1];
    int t  = threadIdx.x;
    int tx = t & 15, ty = t >> 4;
    int m0 = blockIdx.y * BM, n0 = blockIdx.x * BN;
    float acc[8][8];
    #pragma unroll
    for (int i = 0; i < 8; i++)
        #pragma unroll
        for (int j = 0; j < 8; j++) acc[i][j] = 0.0f;

    for (int kk = 0; kk < EMB; kk += BK) {
        #pragma unroll
        for (int p = 0; p < 2; p++) {
            int idx4 = t + p * 256;       // 512 float4 total per tile
            int row = idx4 >> 2;          // 4 float4 per row (16 floats)
            int c4  = idx4 & 3;
            float4 va = *reinterpret_cast<const float4*>(&X[(size_t)(m0+row)*EMB + kk + c4*4]);
            As[c4*4+0][row] = va.x; As[c4*4+1][row] = va.y;
            As[c4*4+2][row] = va.z; As[c4*4+3][row] = va.w;
            float4 vb = *reinterpret_cast<const float4*>(&W[(size_t)(n0+row)*EMB + kk + c4*4]);
            Bs[c4*4+0][row] = vb.x; Bs[c4*4+1][row] = vb.y;
            Bs[c4*4+2][row] = vb.z; Bs[c4*4+3][row] = vb.w;
        }
        __syncthreads();
        #pragma unroll
        for (int k = 0; k < BK; k++) {
            float a[8], b[8];
            #pragma unroll
            for (int i = 0; i < 8; i++) a[i] = As[k][ty + i*16];
            #pragma unroll
            for (int j = 0; j < 8; j++) b[j] = Bs[k][tx + j*16];
            #pragma unroll
            for (int i = 0; i < 8; i++)
                #pragma unroll
                for (int j = 0; j < 8; j++) acc[i][j] += a[i] * b[j];
        }
        __syncthreads();
    }
    #pragma unroll
    for (int i = 0; i < 8; i++) {
        int m = m0 + ty + i*16;
        int b = m >> 11, s = m & 2047;
        #pragma unroll
        for (int j = 0; j < 8; j++) {
            int n = n0 + tx + j*16;
            float v = acc[i][j] + bias[n];
            if (qkvLayout) {
                int h = n >> 6, d = n & 63;
                out[(((size_t)(b*HEADS + h)) * SEQ + s) * HD + d] = v;
            } else {
                out[(size_t)m * EMB + n] = v;
            }
        }
    }
}

// ---------------- flash attention, fp32 ----------------
// One block: 64 query rows of one (b,h). KV tiles of 32. 256 threads (16x16).
#define QT 64
#define KT 32
__global__ __launch_bounds__(256) void flash_kernel(
    const float* __restrict__ Q, const float* __restrict__ K,
    const float* __restrict__ V, float* __restrict__ O)
{
    __shared__ float Qs[HD][QT+1];   // transposed: Qs[d][r]
    __shared__ float Ks[HD][KT+1];   // transposed: Ks[d][c]
    __shared__ float Vs[KT][HD+1];   // Vs[c][d]
    __shared__ float Ss[QT][KT+1];
    __shared__ float mrow[QT], lrow[QT], arow[QT];
    __shared__ float partial[QT][16];

    int t = threadIdx.x;
    int tx = t & 15, ty = t >> 4;
    int bh = blockIdx.y;
    int q0 = blockIdx.x * QT;
    const float* Qb = Q + ((size_t)bh * SEQ + q0) * HD;
    const float* Kb = K + (size_t)bh * SEQ * HD;
    const float* Vb = V + (size_t)bh * SEQ * HD;

    // load Q tile transposed (64x64)
    #pragma unroll
    for (int p = 0; p < 4; p++) {
        int idx4 = t + p * 256;       // 1024 float4
        int row = idx4 >> 4, c4 = idx4 & 15;
        float4 v = *reinterpret_cast<const float4*>(&Qb[(size_t)row*HD + c4*4]);
        Qs[c4*4+0][row] = v.x; Qs[c4*4+1][row] = v.y;
        Qs[c4*4+2][row] = v.z; Qs[c4*4+3][row] = v.w;
    }
    if (t < QT) { mrow[t] = -1e30f; lrow[t] = 0.0f; }

    float acc[4][4];
    #pragma unroll
    for (int i = 0; i < 4; i++)
        #pragma unroll
        for (int j = 0; j < 4; j++) acc[i][j] = 0.0f;

    for (int kt = 0; kt < SEQ; kt += KT) {
        __syncthreads();   // protect smem reuse (Qs on first iter, Ks/Vs/Ss after)
        // load K tile (transposed) and V tile (natural): 32x64 each
        #pragma unroll
        for (int p = 0; p < 2; p++) {
            int idx4 = t + p * 256;   // 512 float4
            int row = idx4 >> 4, c4 = idx4 & 15;
            float4 vk = *reinterpret_cast<const float4*>(&Kb[(size_t)(kt+row)*HD + c4*4]);
            Ks[c4*4+0][row] = vk.x; Ks[c4*4+1][row] = vk.y;
            Ks[c4*4+2][row] = vk.z; Ks[c4*4+3][row] = vk.w;
            float4 vv = *reinterpret_cast<const float4*>(&Vb[(size_t)(kt+row)*HD + c4*4]);
            Vs[row][c4*4+0] = vv.x; Vs[row][c4*4+1] = vv.y;
            Vs[row][c4*4+2] = vv.z; Vs[row][c4*4+3] = vv.w;
        }
        __syncthreads();
        // S = scale * Q K^T (64x32)
        float s[4][2];
        #pragma unroll
        for (int i = 0; i < 4; i++) { s[i][0] = 0.0f; s[i][1] = 0.0f; }
        #pragma unroll
        for (int k = 0; k < HD; k++) {
            float a[4], b[2];
            #pragma unroll
            for (int i = 0; i < 4; i++) a[i] = Qs[k][ty + 16*i];
            #pragma unroll
            for (int j = 0; j < 2; j++) b[j] = Ks[k][tx + 16*j];
            #pragma unroll
            for (int i = 0; i < 4; i++)
                #pragma unroll
                for (int j = 0; j < 2; j++) s[i][j] += a[i] * b[j];
        }
        #pragma unroll
        for (int i = 0; i < 4; i++)
            #pragma unroll
            for (int j = 0; j < 2; j++)
                Ss[ty + 16*i][tx + 16*j] = s[i][j] * 0.125f;
        __syncthreads();
        // phase A: per-row running max + correction factor
        if (t < QT) {
            float mo = mrow[t], mn = mo;
            #pragma unroll 8
            for (int c = 0; c < KT; c++) mn = fmaxf(mn, Ss[t][c]);
            mrow[t] = mn;
            arow[t] = __expf(mo - mn);
        }
        __syncthreads();
        // phase B: exponentiate, partial row sums, rescale accumulators
        float ai[4];
        #pragma unroll
        for (int i = 0; i < 4; i++) {
            int r = ty + 16*i;
            float mr = mrow[r];
            float ps = 0.0f;
            #pragma unroll
            for (int j = 0; j < 2; j++) {
                int c = tx + 16*j;
                float pvv = __expf(Ss[r][c] - mr);
                Ss[r][c] = pvv;
                ps += pvv;
            }
            partial[r][tx] = ps;
            ai[i] = arow[r];
        }
        #pragma unroll
        for (int i = 0; i < 4; i++)
            #pragma unroll
            for (int j = 0; j < 4; j++) acc[i][j] *= ai[i];
        __syncthreads();
        // phase C: finalize row sums (2 warps) — runs concurrently with PV
        if (t < QT) {
            float ssum = 0.0f;
            #pragma unroll
            for (int x = 0; x < 16; x++) ssum += partial[t][x];
            lrow[t] = lrow[t] * arow[t] + ssum;
        }
        // PV: acc += P @ V
        #pragma unroll
        for (int k = 0; k < KT; k++) {
            float pr[4], vr[4];
            #pragma unroll
            for (int i = 0; i < 4; i++) pr[i] = Ss[ty + 16*i][k];
            #pragma unroll
            for (int j = 0; j < 4; j++) vr[j] = Vs[k][tx + 16*j];
            #pragma unroll
            for (int i = 0; i < 4; i++)
                #pragma unroll
                for (int j = 0; j < 4; j++) acc[i][j] += pr[i] * vr[j];
        }
    }
    __syncthreads();
    // epilogue: O in (b,s,e) layout
    int b = bh >> 4, h = bh & 15;
    #pragma unroll
    for (int i = 0; i < 4; i++) {
        int r = ty + 16*i;
        int srow = q0 + r;
        float inv = 1.0f / lrow[r];
        #pragma unroll
        for (int j = 0; j < 4; j++) {
            int d = tx + 16*j;
            O[((size_t)(b*SEQ + srow)) * EMB + h*HD + d] = acc[i][j] * inv;
        }
    }
}

// ---------------- launch ----------------
extern "C" void kernel_launch(void* const* d_in, const int* in_sizes, int n_in,
                              void* d_out, int out_size)
{
    const float* query   = (const float*)d_in[0];
    const float* key     = (const float*)d_in[1];
    const float* value   = (const float*)d_in[2];
    const float* wq      = (const float*)d_in[3];
    const float* bq      = (const float*)d_in[4];
    const float* wk      = (const float*)d_in[5];
    const float* bk      = (const float*)d_in[6];
    const float* wv      = (const float*)d_in[7];
    const float* bv      = (const float*)d_in[8];
    const float* wo      = (const float*)d_in[9];
    const float* bo      = (const float*)d_in[10];
    const float* q_theta = (const float*)d_in[11];
    const float* q_phi   = (const float*)d_in[12];
    const float* q_preW  = (const float*)d_in[13];
    const float* q_preb  = (const float*)d_in[14];
    const float* q_postW = (const float*)d_in[15];
    const float* q_postb = (const float*)d_in[16];
    const float* k_theta = (const float*)d_in[17];
    const float* k_phi   = (const float*)d_in[18];
    const float* k_preW  = (const float*)d_in[19];
    const float* k_preb  = (const float*)d_in[20];
    const float* k_postW = (const float*)d_in[21];
    const float* k_postb = (const float*)d_in[22];

    static float *Q = nullptr, *K, *V, *O, *Wq, *Wk, *Mq, *Mk, *beq, *bek, *bqf, *bkf;
    if (!Q) {
        cudaGetSymbolAddress((void**)&Q,  g_Q);
        cudaGetSymbolAddress((void**)&K,  g_K);
        cudaGetSymbolAddress((void**)&V,  g_V);
        cudaGetSymbolAddress((void**)&O,  g_O);
        cudaGetSymbolAddress((void**)&Wq, g_Wq);
        cudaGetSymbolAddress((void**)&Wk, g_Wk);
        cudaGetSymbolAddress((void**)&Mq, g_Mq);
        cudaGetSymbolAddress((void**)&Mk, g_Mk);
        cudaGetSymbolAddress((void**)&beq, g_beq);
        cudaGetSymbolAddress((void**)&bek, g_bek);
        cudaGetSymbolAddress((void**)&bqf, g_bqf);
        cudaGetSymbolAddress((void**)&bkf, g_bkf);
    }

    // 1) fold the quantum layer into effective projection weights/biases
    quantum_compose<<<1, 256>>>(q_theta, q_phi, q_preW, q_preb, q_postW, q_postb, Mq, beq);
    quantum_compose<<<1, 256>>>(k_theta, k_phi, k_preW, k_preb, k_postW, k_postb, Mk, bek);
    make_weff<<<dim3(4, EMB), 256>>>(Mq, wq, Wq);
    make_weff<<<dim3(4, EMB), 256>>>(Mk, wk, Wk);
    make_beff<<<4, 256>>>(Mq, beq, bq, bqf);
    make_beff<<<4, 256>>>(Mk, bek, bk, bkf);

    // 2) projections -> (b,h,s,d)
    dim3 gg(EMB / BN, NTOK / BM);
    sgemm_kernel<<<gg, 256>>>(query, Wq, bqf, Q, 1);
    sgemm_kernel<<<gg, 256>>>(key,   Wk, bkf, K, 1);
    sgemm_kernel<<<gg, 256>>>(value, wv, bv,  V, 1);

    // 3) attention -> (b,s,e)
    flash_kernel<<<dim3(SEQ / QT, BH), 256>>>(Q, K, V, O);

    // 4) output projection
    sgemm_kernel<<<gg, 256>>>(O, wo, bo, (float*)d_out, 0);
}

// round 4
// speedup vs baseline: 1.6515x; 1.6515x over previous
#include <cuda_runtime.h>
#include <math.h>
#include <stdint.h>

// Problem constants
#define BATCH 4
#define SEQ   2048
#define EMB   1024
#define HEADS 16
#define HD    64
#define NTOK  (BATCH*SEQ)     // 8192
#define BH    (BATCH*HEADS)   // 64
#define NQUBITS 6

// ---------------- scratch (static device globals; no allocation) ----------------
__device__ float g_Q[BH*SEQ*HD];       // (b,h,s,d)
__device__ float g_K[BH*SEQ*HD];
__device__ float g_V[BH*SEQ*HD];
__device__ float g_O[NTOK*EMB];        // (b,s,e)
__device__ float g_Wq[EMB*EMB];
__device__ float g_Wk[EMB*EMB];
__device__ float g_Mq[HD*HD];
__device__ float g_Mk[HD*HD];
__device__ float g_beq[HD];
__device__ float g_bek[HD];
__device__ float g_bqf[EMB];
__device__ float g_bkf[EMB];

// ---------------- tf32 helpers ----------------
__device__ __forceinline__ uint32_t f2tf(float x) {
    uint32_t u; asm("cvt.rna.tf32.f32 %0, %1;" : "=r"(u) : "f"(x)); return u;
}
__device__ __forceinline__ void split2(float x, float& h, float& l) {
    h = __uint_as_float(f2tf(x));
    l = __uint_as_float(f2tf(x - h));
}
__device__ __forceinline__ void mma_tf32(float* d, const uint32_t* a, const uint32_t* b) {
    asm volatile("mma.sync.aligned.m16n8k8.row.col.f32.tf32.tf32.f32 "
        "{%0,%1,%2,%3}, {%4,%5,%6,%7}, {%8,%9}, {%0,%1,%2,%3};"
        : "+f"(d[0]), "+f"(d[1]), "+f"(d[2]), "+f"(d[3])
        : "r"(a[0]), "r"(a[1]), "r"(a[2]), "r"(a[3]), "r"(b[0]), "r"(b[1]));
}
__device__ __forceinline__ uint32_t fbits(float x) { return __float_as_uint(x); }

// ---------------- quantum layer composition (unchanged, fp32-exact) ----------------
__global__ __launch_bounds__(256) void quantum_compose(
    const float* __restrict__ theta, const float* __restrict__ phi,
    const float* __restrict__ preW, const float* __restrict__ preb,
    const float* __restrict__ postW, const float* __restrict__ postb,
    float* __restrict__ Meff, float* __restrict__ beff)
{
    __shared__ float A[HD][HD+1];
    __shared__ float bv[HD];
    int t = threadIdx.x;
    for (int idx = t; idx < HD*HD; idx += 256) A[idx >> 6][idx & 63] = preW[idx];
    if (t < HD) bv[t] = preb[t];
    __syncthreads();
    for (int i = 0; i < NQUBITS; i++) {
        float th = theta[i], ph = phi[i];
        float c = cosf(th), s = sinf(th), cp = cosf(ph);
        for (int w = t; w < 32*HD; w += 256) {
            int p = w >> 6, col = w & 63;
            int low = p & ((1 << i) - 1);
            int i0 = ((p >> i) << (i + 1)) | low;
            int i1 = i0 | (1 << i);
            float x0 = A[i0][col], x1 = A[i1][col];
            A[i0][col] = c * x0 - s * x1;
            A[i1][col] = cp * (s * x0 + c * x1);
        }
        if (t < 32) {
            int p = t;
            int low = p & ((1 << i) - 1);
            int i0 = ((p >> i) << (i + 1)) | low;
            int i1 = i0 | (1 << i);
            float x0 = bv[i0], x1 = bv[i1];
            bv[i0] = c * x0 - s * x1;
            bv[i1] = cp * (s * x0 + c * x1);
        }
        __syncthreads();
    }
    for (int idx = t; idx < HD*HD; idx += 256) {
        int i = idx >> 6, j = idx & 63;
        float acc = (i == j) ? 1.0f : 0.0f;
        #pragma unroll 8
        for (int d = 0; d < HD; d++) acc += postW[i*HD + d] * A[d][j];
        Meff[idx] = acc;
    }
    if (t < HD) {
        float acc = postb[t];
        #pragma unroll 8
        for (int d = 0; d < HD; d++) acc += postW[t*HD + d] * bv[d];
        beff[t] = acc;
    }
}

__global__ __launch_bounds__(256) void make_weff(
    const float* __restrict__ M, const float* __restrict__ w, float* __restrict__ weff)
{
    int r = blockIdx.y;
    int j = blockIdx.x * 256 + threadIdx.x;
    int h = r >> 6, i = r & 63;
    __shared__ float Mrow[HD];
    if (threadIdx.x < HD) Mrow[threadIdx.x] = M[i*HD + threadIdx.x];
    __syncthreads();
    float acc = 0.0f;
    #pragma unroll 8
    for (int d = 0; d < HD; d++) acc += Mrow[d] * w[(h*HD + d) * EMB + j];
    weff[(size_t)r * EMB + j] = acc;
}

__global__ __launch_bounds__(256) void make_beff(
    const float* __restrict__ M, const float* __restrict__ beff,
    const float* __restrict__ b_in, float* __restrict__ bfull)
{
    int r = blockIdx.x * 256 + threadIdx.x;
    int h = r >> 6, i = r & 63;
    float acc = beff[i];
    #pragma unroll 8
    for (int d = 0; d < HD; d++) acc += M[i*HD + d] * b_in[h*HD + d];
    bfull[r] = acc;
}

// ---------------- 3xTF32 tensor-core GEMM ----------------
// C(8192x1024) = X @ W^T + bias. BM=BN=128, BK=16, 8 warps (2x4), warp tile 64x32.
#define BM 128
#define BN 128
#define BK 16
#define BKP 20   // k-stride pad: frag reads land on distinct banks mod 32
__global__ __launch_bounds__(256) void gemm3x(
    const float* __restrict__ X, const float* __restrict__ W,
    const float* __restrict__ bias, float* __restrict__ out, int qkvLayout)
{
    __shared__ float Ah[BM][BKP], Al[BM][BKP];
    __shared__ float Bh[BN][BKP], Bl[BN][BKP];
    int t = threadIdx.x;
    int lane = t & 31, w = t >> 5;
    int gid = lane >> 2, tig = lane & 3;
    int wm = w >> 2, wn = w & 3;           // 2 x 4 warp grid
    int m0 = blockIdx.y * BM, n0 = blockIdx.x * BN;

    float acc[4][4][4];
    #pragma unroll
    for (int i = 0; i < 4; i++)
        #pragma unroll
        for (int j = 0; j < 4; j++)
            #pragma unroll
            for (int r = 0; r < 4; r++) acc[i][j][r] = 0.0f;

    for (int kk = 0; kk < EMB; kk += BK) {
        #pragma unroll
        for (int p = 0; p < 2; p++) {
            int idx4 = t + p * 256;
            int row = idx4 >> 2, c4 = idx4 & 3;
            float4 va = *reinterpret_cast<const float4*>(&X[(size_t)(m0+row)*EMB + kk + c4*4]);
            float4 hA, lA;
            split2(va.x, hA.x, lA.x); split2(va.y, hA.y, lA.y);
            split2(va.z, hA.z, lA.z); split2(va.w, hA.w, lA.w);
            *reinterpret_cast<float4*>(&Ah[row][c4*4]) = hA;
            *reinterpret_cast<float4*>(&Al[row][c4*4]) = lA;
            float4 vb = *reinterpret_cast<const float4*>(&W[(size_t)(n0+row)*EMB + kk + c4*4]);
            float4 hB, lB;
            split2(vb.x, hB.x, lB.x); split2(vb.y, hB.y, lB.y);
            split2(vb.z, hB.z, lB.z); split2(vb.w, hB.w, lB.w);
            *reinterpret_cast<float4*>(&Bh[row][c4*4]) = hB;
            *reinterpret_cast<float4*>(&Bl[row][c4*4]) = lB;
        }
        __syncthreads();
        #pragma unroll
        for (int ks = 0; ks < 2; ks++) {
            int kb = ks * 8;
            uint32_t ah[4][4], al[4][4];
            #pragma unroll
            for (int mt = 0; mt < 4; mt++) {
                int mr = wm*64 + mt*16;
                ah[mt][0] = fbits(Ah[mr+gid  ][kb+tig  ]);
                ah[mt][1] = fbits(Ah[mr+gid+8][kb+tig  ]);
                ah[mt][2] = fbits(Ah[mr+gid  ][kb+tig+4]);
                ah[mt][3] = fbits(Ah[mr+gid+8][kb+tig+4]);
                al[mt][0] = fbits(Al[mr+gid  ][kb+tig  ]);
                al[mt][1] = fbits(Al[mr+gid+8][kb+tig  ]);
                al[mt][2] = fbits(Al[mr+gid  ][kb+tig+4]);
                al[mt][3] = fbits(Al[mr+gid+8][kb+tig+4]);
            }
            uint32_t bh[4][2], bl[4][2];
            #pragma unroll
            for (int nt = 0; nt < 4; nt++) {
                int nc = wn*32 + nt*8;
                bh[nt][0] = fbits(Bh[nc+gid][kb+tig  ]);
                bh[nt][1] = fbits(Bh[nc+gid][kb+tig+4]);
                bl[nt][0] = fbits(Bl[nc+gid][kb+tig  ]);
                bl[nt][1] = fbits(Bl[nc+gid][kb+tig+4]);
            }
            #pragma unroll
            for (int mt = 0; mt < 4; mt++)
                #pragma unroll
                for (int nt = 0; nt < 4; nt++) {
                    mma_tf32(acc[mt][nt], ah[mt], bh[nt]);
                    mma_tf32(acc[mt][nt], al[mt], bh[nt]);
                    mma_tf32(acc[mt][nt], ah[mt], bl[nt]);
                }
        }
        __syncthreads();
    }
    // epilogue
    #pragma unroll
    for (int mt = 0; mt < 4; mt++) {
        int m = m0 + wm*64 + mt*16 + gid;
        #pragma unroll
        for (int nt = 0; nt < 4; nt++) {
            int n = n0 + wn*32 + nt*8 + tig*2;
            float b0 = bias[n], b1 = bias[n+1];
            float2 v0 = make_float2(acc[mt][nt][0] + b0, acc[mt][nt][1] + b1);
            float2 v1 = make_float2(acc[mt][nt][2] + b0, acc[mt][nt][3] + b1);
            if (qkvLayout) {
                int bb = m >> 11, s = m & 2047;
                int h = n >> 6, d = n & 63;
                *reinterpret_cast<float2*>(&out[(((size_t)(bb*HEADS + h)) * SEQ + s) * HD + d]) = v0;
                int m1 = m + 8;
                int bb1 = m1 >> 11, s1 = m1 & 2047;
                *reinterpret_cast<float2*>(&out[(((size_t)(bb1*HEADS + h)) * SEQ + s1) * HD + d]) = v1;
            } else {
                *reinterpret_cast<float2*>(&out[(size_t)m * EMB + n]) = v0;
                *reinterpret_cast<float2*>(&out[(size_t)(m+8) * EMB + n]) = v1;
            }
        }
    }
}

// ---------------- 3xTF32 flash attention ----------------
// Block: 128 q-rows of one (b,h), 8 warps x 16 rows. KV tiles of 32. Register softmax.
// dyn smem layout (floats):
//   KH [32][68]  @ 0      (2176)
//   KL [32][68]  @ 2176
//   VH [32][72]  @ 4352   (2304)
//   VL [32][72]  @ 6656
//   PS [128][36] @ 8960   (4608)    total 13568 floats = 54272 B
//   Q stage overlays [128][68] at 0 (8704 floats)
#define FL_SMEM_BYTES 54272
__global__ __launch_bounds__(256) void flash3x(
    const float* __restrict__ Q, const float* __restrict__ K,
    const float* __restrict__ V, float* __restrict__ O)
{
    extern __shared__ float dsm[];
    float (*KH)[68] = reinterpret_cast<float(*)[68]>(dsm);
    float (*KL)[68] = reinterpret_cast<float(*)[68]>(dsm + 2176);
    float (*VH)[72] = reinterpret_cast<float(*)[72]>(dsm + 4352);
    float (*VL)[72] = reinterpret_cast<float(*)[72]>(dsm + 6656);
    float (*PS)[36] = reinterpret_cast<float(*)[36]>(dsm + 8960);
    float (*QS)[68] = reinterpret_cast<float(*)[68]>(dsm);

    int t = threadIdx.x;
    int lane = t & 31, w = t >> 5;
    int gid = lane >> 2, tig = lane & 3;
    int bh_ = blockIdx.y;
    int q0 = blockIdx.x * 128;
    const float* Qb = Q + ((size_t)bh_ * SEQ + q0) * HD;
    const float* Kb = K + (size_t)bh_ * SEQ * HD;
    const float* Vb = V + (size_t)bh_ * SEQ * HD;

    // stage Q (raw fp32), then extract hi/lo fragments to registers
    #pragma unroll
    for (int p = 0; p < 8; p++) {
        int idx4 = t + p * 256;
        int row = idx4 >> 4, c4 = idx4 & 15;
        float4 v = *reinterpret_cast<const float4*>(&Qb[(size_t)row*HD + c4*4]);
        *reinterpret_cast<float4*>(&QS[row][c4*4]) = v;
    }
    __syncthreads();
    uint32_t qh[8][4], ql[8][4];
    {
        int r0 = w * 16 + gid;
        #pragma unroll
        for (int kq = 0; kq < 8; kq++) {
            float x0 = QS[r0  ][kq*8+tig  ];
            float x1 = QS[r0+8][kq*8+tig  ];
            float x2 = QS[r0  ][kq*8+tig+4];
            float x3 = QS[r0+8][kq*8+tig+4];
            float h, l;
            split2(x0, h, l); qh[kq][0] = fbits(h); ql[kq][0] = fbits(l);
            split2(x1, h, l); qh[kq][1] = fbits(h); ql[kq][1] = fbits(l);
            split2(x2, h, l); qh[kq][2] = fbits(h); ql[kq][2] = fbits(l);
            split2(x3, h, l); qh[kq][3] = fbits(h); ql[kq][3] = fbits(l);
        }
    }

    float o[8][4];
    #pragma unroll
    for (int i = 0; i < 8; i++)
        #pragma unroll
        for (int j = 0; j < 4; j++) o[i][j] = 0.0f;
    float m0v = -1e30f, m1v = -1e30f, l0 = 0.0f, l1 = 0.0f;
    const float SCALE = 0.125f;

    for (int kt = 0; kt < SEQ; kt += 32) {
        __syncthreads();   // frag reads / prior PV done before overwriting K/V (and QS on iter 0)
        #pragma unroll
        for (int p = 0; p < 2; p++) {
            int idx4 = t + p * 256;
            int row = idx4 >> 4, c4 = idx4 & 15;
            float4 kv = *reinterpret_cast<const float4*>(&Kb[(size_t)(kt+row)*HD + c4*4]);
            float4 hK, lK;
            split2(kv.x, hK.x, lK.x); split2(kv.y, hK.y, lK.y);
            split2(kv.z, hK.z, lK.z); split2(kv.w, hK.w, lK.w);
            *reinterpret_cast<float4*>(&KH[row][c4*4]) = hK;
            *reinterpret_cast<float4*>(&KL[row][c4*4]) = lK;
            float4 vv = *reinterpret_cast<const float4*>(&Vb[(size_t)(kt+row)*HD + c4*4]);
            float4 hV, lV;
            split2(vv.x, hV.x, lV.x); split2(vv.y, hV.y, lV.y);
            split2(vv.z, hV.z, lV.z); split2(vv.w, hV.w, lV.w);
            *reinterpret_cast<float4*>(&VH[row][c4*4]) = hV;
            *reinterpret_cast<float4*>(&VL[row][c4*4]) = lV;
        }
        __syncthreads();

        // S = Q @ K^T  (16 rows x 32 cols per warp), 3xTF32
        float s[4][4];
        #pragma unroll
        for (int nt = 0; nt < 4; nt++)
            #pragma unroll
            for (int r = 0; r < 4; r++) s[nt][r] = 0.0f;
        #pragma unroll
        for (int kq = 0; kq < 8; kq++) {
            uint32_t bhf[4][2], blf[4][2];
            #pragma unroll
            for (int nt = 0; nt < 4; nt++) {
                int nc = nt * 8;
                bhf[nt][0] = fbits(KH[nc+gid][kq*8+tig  ]);
                bhf[nt][1] = fbits(KH[nc+gid][kq*8+tig+4]);
                blf[nt][0] = fbits(KL[nc+gid][kq*8+tig  ]);
                blf[nt][1] = fbits(KL[nc+gid][kq*8+tig+4]);
            }
            #pragma unroll
            for (int nt = 0; nt < 4; nt++) {
                mma_tf32(s[nt], qh[kq], bhf[nt]);
                mma_tf32(s[nt], ql[kq], bhf[nt]);
                mma_tf32(s[nt], qh[kq], blf[nt]);
            }
        }

        // register softmax: thread owns rows (w*16+gid) and (+8), 8 cols each
        float tm0 = -1e30f, tm1 = -1e30f;
        #pragma unroll
        for (int nt = 0; nt < 4; nt++) {
            tm0 = fmaxf(tm0, fmaxf(s[nt][0], s[nt][1]));
            tm1 = fmaxf(tm1, fmaxf(s[nt][2], s[nt][3]));
        }
        tm0 *= SCALE; tm1 *= SCALE;
        tm0 = fmaxf(tm0, __shfl_xor_sync(0xffffffffu, tm0, 1));
        tm0 = fmaxf(tm0, __shfl_xor_sync(0xffffffffu, tm0, 2));
        tm1 = fmaxf(tm1, __shfl_xor_sync(0xffffffffu, tm1, 1));
        tm1 = fmaxf(tm1, __shfl_xor_sync(0xffffffffu, tm1, 2));
        float mn0 = fmaxf(m0v, tm0), mn1 = fmaxf(m1v, tm1);
        float a0s = __expf(m0v - mn0), a1s = __expf(m1v - mn1);
        m0v = mn0; m1v = mn1;
        float rs0 = 0.0f, rs1 = 0.0f;
        int prow = w * 16 + gid;
        #pragma unroll
        for (int nt = 0; nt < 4; nt++) {
            float p0 = __expf(s[nt][0]*SCALE - mn0);
            float p1 = __expf(s[nt][1]*SCALE - mn0);
            float p2 = __expf(s[nt][2]*SCALE - mn1);
            float p3 = __expf(s[nt][3]*SCALE - mn1);
            rs0 += p0 + p1; rs1 += p2 + p3;
            int col = nt*8 + tig*2;
            PS[prow  ][col]   = __uint_as_float(f2tf(p0));
            PS[prow  ][col+1] = __uint_as_float(f2tf(p1));
            PS[prow+8][col]   = __uint_as_float(f2tf(p2));
            PS[prow+8][col+1] = __uint_as_float(f2tf(p3));
        }
        rs0 += __shfl_xor_sync(0xffffffffu, rs0, 1);
        rs0 += __shfl_xor_sync(0xffffffffu, rs0, 2);
        rs1 += __shfl_xor_sync(0xffffffffu, rs1, 1);
        rs1 += __shfl_xor_sync(0xffffffffu, rs1, 2);
        l0 = l0 * a0s + rs0;
        l1 = l1 * a1s + rs1;
        #pragma unroll
        for (int nt = 0; nt < 8; nt++) {
            o[nt][0] *= a0s; o[nt][1] *= a0s;
            o[nt][2] *= a1s; o[nt][3] *= a1s;
        }
        __syncwarp();

        // O += P @ V   (P single-tf32, V hi+lo -> 2 mma per tile)
        #pragma unroll
        for (int kp = 0; kp < 4; kp++) {
            uint32_t af[4];
            af[0] = fbits(PS[prow  ][kp*8+tig  ]);
            af[1] = fbits(PS[prow+8][kp*8+tig  ]);
            af[2] = fbits(PS[prow  ][kp*8+tig+4]);
            af[3] = fbits(PS[prow+8][kp*8+tig+4]);
            #pragma unroll
            for (int nt = 0; nt < 8; nt++) {
                uint32_t bv2[2], bl2[2];
                bv2[0] = fbits(VH[kp*8+tig  ][nt*8+gid]);
                bv2[1] = fbits(VH[kp*8+tig+4][nt*8+gid]);
                bl2[0] = fbits(VL[kp*8+tig  ][nt*8+gid]);
                bl2[1] = fbits(VL[kp*8+tig+4][nt*8+gid]);
                mma_tf32(o[nt], af, bv2);
                mma_tf32(o[nt], af, bl2);
            }
        }
    }

    // epilogue -> O in (b,s,e) layout
    float inv0 = 1.0f / l0, inv1 = 1.0f / l1;
    int b = bh_ >> 4, h = bh_ & 15;
    int grow = q0 + w * 16 + gid;
    #pragma unroll
    for (int nt = 0; nt < 8; nt++) {
        int col = h*HD + nt*8 + tig*2;
        float2 v0 = make_float2(o[nt][0]*inv0, o[nt][1]*inv0);
        float2 v1 = make_float2(o[nt][2]*inv1, o[nt][3]*inv1);
        *reinterpret_cast<float2*>(&O[((size_t)(b*SEQ + grow)) * EMB + col]) = v0;
        *reinterpret_cast<float2*>(&O[((size_t)(b*SEQ + grow + 8)) * EMB + col]) = v1;
    }
}

// ---------------- launch ----------------
extern "C" void kernel_launch(void* const* d_in, const int* in_sizes, int n_in,
                              void* d_out, int out_size)
{
    const float* query   = (const float*)d_in[0];
    const float* key     = (const float*)d_in[1];
    const float* value   = (const float*)d_in[2];
    const float* wq      = (const float*)d_in[3];
    const float* bq      = (const float*)d_in[4];
    const float* wk      = (const float*)d_in[5];
    const float* bk      = (const float*)d_in[6];
    const float* wv      = (const float*)d_in[7];
    const float* bv      = (const float*)d_in[8];
    const float* wo      = (const float*)d_in[9];
    const float* bo      = (const float*)d_in[10];
    const float* q_theta = (const float*)d_in[11];
    const float* q_phi   = (const float*)d_in[12];
    const float* q_preW  = (const float*)d_in[13];
    const float* q_preb  = (const float*)d_in[14];
    const float* q_postW = (const float*)d_in[15];
    const float* q_postb = (const float*)d_in[16];
    const float* k_theta = (const float*)d_in[17];
    const float* k_phi   = (const float*)d_in[18];
    const float* k_preW  = (const float*)d_in[19];
    const float* k_preb  = (const float*)d_in[20];
    const float* k_postW = (const float*)d_in[21];
    const float* k_postb = (const float*)d_in[22];

    static float *Q = nullptr, *K, *V, *O, *Wq, *Wk, *Mq, *Mk, *beq, *bek, *bqf, *bkf;
    if (!Q) {
        cudaGetSymbolAddress((void**)&Q,  g_Q);
        cudaGetSymbolAddress((void**)&K,  g_K);
        cudaGetSymbolAddress((void**)&V,  g_V);
        cudaGetSymbolAddress((void**)&O,  g_O);
        cudaGetSymbolAddress((void**)&Wq, g_Wq);
        cudaGetSymbolAddress((void**)&Wk, g_Wk);
        cudaGetSymbolAddress((void**)&Mq, g_Mq);
        cudaGetSymbolAddress((void**)&Mk, g_Mk);
        cudaGetSymbolAddress((void**)&beq, g_beq);
        cudaGetSymbolAddress((void**)&bek, g_bek);
        cudaGetSymbolAddress((void**)&bqf, g_bqf);
        cudaGetSymbolAddress((void**)&bkf, g_bkf);
        cudaFuncSetAttribute(flash3x, cudaFuncAttributeMaxDynamicSharedMemorySize, FL_SMEM_BYTES);
    }

    // 1) fold the quantum layer into effective projection weights/biases
    quantum_compose<<<1, 256>>>(q_theta, q_phi, q_preW, q_preb, q_postW, q_postb, Mq, beq);
    quantum_compose<<<1, 256>>>(k_theta, k_phi, k_preW, k_preb, k_postW, k_postb, Mk, bek);
    make_weff<<<dim3(4, EMB), 256>>>(Mq, wq, Wq);
    make_weff<<<dim3(4, EMB), 256>>>(Mk, wk, Wk);
    make_beff<<<4, 256>>>(Mq, beq, bq, bqf);
    make_beff<<<4, 256>>>(Mk, bek, bk, bkf);

    // 2) projections -> (b,h,s,d), 3xTF32 tensor cores
    dim3 gg(EMB / BN, NTOK / BM);
    gemm3x<<<gg, 256>>>(query, Wq, bqf, Q, 1);
    gemm3x<<<gg, 256>>>(key,   Wk, bkf, K, 1);
    gemm3x<<<gg, 256>>>(value, wv, bv,  V, 1);

    // 3) attention -> (b,s,e)
    flash3x<<<dim3(SEQ / 128, BH), 256, FL_SMEM_BYTES>>>(Q, K, V, O);

    // 4) output projection
    gemm3x<<<gg, 256>>>(O, wo, bo, (float*)d_out, 0);
}

// round 5
// speedup vs baseline: 2.0909x; 1.2661x over previous
#include <cuda_runtime.h>
#include <math.h>
#include <stdint.h>

// Problem constants
#define BATCH 4
#define SEQ   2048
#define EMB   1024
#define HEADS 16
#define HD    64
#define NTOK  (BATCH*SEQ)     // 8192
#define BH    (BATCH*HEADS)   // 64
#define NQUBITS 6

// ---------------- scratch (static device globals; no allocation) ----------------
__device__ float g_Q[BH*SEQ*HD];       // (b,h,s,d) raw fp32
__device__ float g_Kh[BH*SEQ*HD];      // tf32 hi of K
__device__ float g_Kl[BH*SEQ*HD];      // tf32 lo of K
__device__ float g_Vh[BH*SEQ*HD];      // tf32-rounded V
__device__ float g_O[NTOK*EMB];        // (b,s,e)
__device__ float g_Wq[EMB*EMB];
__device__ float g_Wk[EMB*EMB];
__device__ float g_Mq[HD*HD];
__device__ float g_Mk[HD*HD];
__device__ float g_beq[HD];
__device__ float g_bek[HD];
__device__ float g_bqf[EMB];
__device__ float g_bkf[EMB];

// ---------------- tf32 / cp.async helpers ----------------
__device__ __forceinline__ uint32_t f2tf(float x) {
    uint32_t u; asm("cvt.rna.tf32.f32 %0, %1;" : "=r"(u) : "f"(x)); return u;
}
__device__ __forceinline__ void split2(float x, float& h, float& l) {
    h = __uint_as_float(f2tf(x));
    l = __uint_as_float(f2tf(x - h));
}
__device__ __forceinline__ void mma_tf32(float* d, const uint32_t* a, const uint32_t* b) {
    asm volatile("mma.sync.aligned.m16n8k8.row.col.f32.tf32.tf32.f32 "
        "{%0,%1,%2,%3}, {%4,%5,%6,%7}, {%8,%9}, {%0,%1,%2,%3};"
        : "+f"(d[0]), "+f"(d[1]), "+f"(d[2]), "+f"(d[3])
        : "r"(a[0]), "r"(a[1]), "r"(a[2]), "r"(a[3]), "r"(b[0]), "r"(b[1]));
}
__device__ __forceinline__ uint32_t fbits(float x) { return __float_as_uint(x); }
__device__ __forceinline__ void cp16(void* s, const void* g) {
    asm volatile("cp.async.cg.shared.global [%0], [%1], 16;"
        :: "r"((uint32_t)__cvta_generic_to_shared(s)), "l"(g));
}
__device__ __forceinline__ void cp_commit() { asm volatile("cp.async.commit_group;"); }
__device__ __forceinline__ void cp_wait1() { asm volatile("cp.async.wait_group 1;"); }
__device__ __forceinline__ void cp_wait0() { asm volatile("cp.async.wait_group 0;"); }

// ---------------- quantum layer composition (fp32-exact) ----------------
__global__ __launch_bounds__(256) void quantum_compose(
    const float* __restrict__ theta, const float* __restrict__ phi,
    const float* __restrict__ preW, const float* __restrict__ preb,
    const float* __restrict__ postW, const float* __restrict__ postb,
    float* __restrict__ Meff, float* __restrict__ beff)
{
    __shared__ float A[HD][HD+1];
    __shared__ float bv[HD];
    int t = threadIdx.x;
    for (int idx = t; idx < HD*HD; idx += 256) A[idx >> 6][idx & 63] = preW[idx];
    if (t < HD) bv[t] = preb[t];
    __syncthreads();
    for (int i = 0; i < NQUBITS; i++) {
        float th = theta[i], ph = phi[i];
        float c = cosf(th), s = sinf(th), cp = cosf(ph);
        for (int w = t; w < 32*HD; w += 256) {
            int p = w >> 6, col = w & 63;
            int low = p & ((1 << i) - 1);
            int i0 = ((p >> i) << (i + 1)) | low;
            int i1 = i0 | (1 << i);
            float x0 = A[i0][col], x1 = A[i1][col];
            A[i0][col] = c * x0 - s * x1;
            A[i1][col] = cp * (s * x0 + c * x1);
        }
        if (t < 32) {
            int p = t;
            int low = p & ((1 << i) - 1);
            int i0 = ((p >> i) << (i + 1)) | low;
            int i1 = i0 | (1 << i);
            float x0 = bv[i0], x1 = bv[i1];
            bv[i0] = c * x0 - s * x1;
            bv[i1] = cp * (s * x0 + c * x1);
        }
        __syncthreads();
    }
    for (int idx = t; idx < HD*HD; idx += 256) {
        int i = idx >> 6, j = idx & 63;
        float acc = (i == j) ? 1.0f : 0.0f;
        #pragma unroll 8
        for (int d = 0; d < HD; d++) acc += postW[i*HD + d] * A[d][j];
        Meff[idx] = acc;
    }
    if (t < HD) {
        float acc = postb[t];
        #pragma unroll 8
        for (int d = 0; d < HD; d++) acc += postW[t*HD + d] * bv[d];
        beff[t] = acc;
    }
}

__global__ __launch_bounds__(256) void make_weff(
    const float* __restrict__ M, const float* __restrict__ w, float* __restrict__ weff)
{
    int r = blockIdx.y;
    int j = blockIdx.x * 256 + threadIdx.x;
    int h = r >> 6, i = r & 63;
    __shared__ float Mrow[HD];
    if (threadIdx.x < HD) Mrow[threadIdx.x] = M[i*HD + threadIdx.x];
    __syncthreads();
    float acc = 0.0f;
    #pragma unroll 8
    for (int d = 0; d < HD; d++) acc += Mrow[d] * w[(h*HD + d) * EMB + j];
    weff[(size_t)r * EMB + j] = acc;
}

__global__ __launch_bounds__(256) void make_beff(
    const float* __restrict__ M, const float* __restrict__ beff,
    const float* __restrict__ b_in, float* __restrict__ bfull)
{
    int r = blockIdx.x * 256 + threadIdx.x;
    int h = r >> 6, i = r & 63;
    float acc = beff[i];
    #pragma unroll 8
    for (int d = 0; d < HD; d++) acc += M[i*HD + d] * b_in[h*HD + d];
    bfull[r] = acc;
}

// ---------------- 3xTF32 tensor-core GEMM, cp.async double-buffered ----------------
// C(8192x1024) = X @ W^T + bias. BM=BN=128, BK=16, 8 warps (2x4), warp tile 64x32.
// Raw fp32 staged in smem; hi/lo split at fragment-build time.
// mode: 0 = flat raw (m,n); 1 = qkv scatter raw; 2 = qkv scatter split hi->out, lo->out2;
//       3 = qkv scatter tf32-rounded.
#define BM 128
#define BN 128
#define BK 16
#define BKP 20   // pad: frag reads land on distinct banks mod 32
__global__ __launch_bounds__(256) void gemm3x(
    const float* __restrict__ X, const float* __restrict__ W,
    const float* __restrict__ bias, float* __restrict__ out,
    float* __restrict__ out2, int mode)
{
    __shared__ float sm[2 * 2 * BM * BKP];   // 2 stages x (A + B) x 128x20 = 40KB
    int t = threadIdx.x;
    int lane = t & 31, w = t >> 5;
    int gid = lane >> 2, tig = lane & 3;
    int wm = w >> 2, wn = w & 3;           // 2 x 4 warp grid
    int m0 = blockIdx.y * BM, n0 = blockIdx.x * BN;

    float acc[4][4][4];
    #pragma unroll
    for (int i = 0; i < 4; i++)
        #pragma unroll
        for (int j = 0; j < 4; j++)
            #pragma unroll
            for (int r = 0; r < 4; r++) acc[i][j][r] = 0.0f;

    // per-thread copy coordinates (A: 512 chunks, B: 512 chunks, 4 per thread)
    int crow0 = (t      ) >> 2, cc0 = (t      ) & 3;
    int crow1 = (t + 256) >> 2, cc1 = (t + 256) & 3;

    const int NSLAB = EMB / BK;  // 64
    // prologue: slab 0 -> stage 0
    {
        float* dA = sm; float* dB = sm + BM*BKP;
        cp16(dA + crow0*BKP + cc0*4, X + (size_t)(m0+crow0)*EMB + cc0*4);
        cp16(dA + crow1*BKP + cc1*4, X + (size_t)(m0+crow1)*EMB + cc1*4);
        cp16(dB + crow0*BKP + cc0*4, W + (size_t)(n0+crow0)*EMB + cc0*4);
        cp16(dB + crow1*BKP + cc1*4, W + (size_t)(n0+crow1)*EMB + cc1*4);
        cp_commit();
    }

    for (int s = 0; s < NSLAB; s++) {
        if (s + 1 < NSLAB) {
            int st = (s + 1) & 1;
            int kk = (s + 1) * BK;
            float* dA = sm + st * 2 * BM * BKP;
            float* dB = dA + BM * BKP;
            cp16(dA + crow0*BKP + cc0*4, X + (size_t)(m0+crow0)*EMB + kk + cc0*4);
            cp16(dA + crow1*BKP + cc1*4, X + (size_t)(m0+crow1)*EMB + kk + cc1*4);
            cp16(dB + crow0*BKP + cc0*4, W + (size_t)(n0+crow0)*EMB + kk + cc0*4);
            cp16(dB + crow1*BKP + cc1*4, W + (size_t)(n0+crow1)*EMB + kk + cc1*4);
            cp_commit();
            cp_wait1();
        } else {
            cp_wait0();
        }
        __syncthreads();
        float* dA = sm + (s & 1) * 2 * BM * BKP;
        float* dB = dA + BM * BKP;
        #pragma unroll
        for (int ks = 0; ks < 2; ks++) {
            int kb = ks * 8;
            uint32_t ah[4][4], al[4][4];
            #pragma unroll
            for (int mt = 0; mt < 4; mt++) {
                int mr = wm*64 + mt*16;
                float h, l;
                split2(dA[(mr+gid  )*BKP + kb+tig  ], h, l); ah[mt][0]=fbits(h); al[mt][0]=fbits(l);
                split2(dA[(mr+gid+8)*BKP + kb+tig  ], h, l); ah[mt][1]=fbits(h); al[mt][1]=fbits(l);
                split2(dA[(mr+gid  )*BKP + kb+tig+4], h, l); ah[mt][2]=fbits(h); al[mt][2]=fbits(l);
                split2(dA[(mr+gid+8)*BKP + kb+tig+4], h, l); ah[mt][3]=fbits(h); al[mt][3]=fbits(l);
            }
            uint32_t bh[4][2], bl[4][2];
            #pragma unroll
            for (int nt = 0; nt < 4; nt++) {
                int nc = wn*32 + nt*8;
                float h, l;
                split2(dB[(nc+gid)*BKP + kb+tig  ], h, l); bh[nt][0]=fbits(h); bl[nt][0]=fbits(l);
                split2(dB[(nc+gid)*BKP + kb+tig+4], h, l); bh[nt][1]=fbits(h); bl[nt][1]=fbits(l);
            }
            #pragma unroll
            for (int mt = 0; mt < 4; mt++)
                #pragma unroll
                for (int nt = 0; nt < 4; nt++) {
                    mma_tf32(acc[mt][nt], ah[mt], bh[nt]);
                    mma_tf32(acc[mt][nt], al[mt], bh[nt]);
                    mma_tf32(acc[mt][nt], ah[mt], bl[nt]);
                }
        }
        __syncthreads();
    }

    // epilogue
    #pragma unroll
    for (int mt = 0; mt < 4; mt++) {
        int m = m0 + wm*64 + mt*16 + gid;
        #pragma unroll
        for (int nt = 0; nt < 4; nt++) {
            int n = n0 + wn*32 + nt*8 + tig*2;
            float b0 = bias[n], b1 = bias[n+1];
            float va0 = acc[mt][nt][0] + b0, va1 = acc[mt][nt][1] + b1;
            float vb0 = acc[mt][nt][2] + b0, vb1 = acc[mt][nt][3] + b1;
            if (mode == 0) {
                *reinterpret_cast<float2*>(&out[(size_t)m * EMB + n]) = make_float2(va0, va1);
                *reinterpret_cast<float2*>(&out[(size_t)(m+8) * EMB + n]) = make_float2(vb0, vb1);
            } else {
                int h = n >> 6, d = n & 63;
                int bb0 = m >> 11, s0 = m & 2047;
                int m1 = m + 8;
                int bb1 = m1 >> 11, s1 = m1 & 2047;
                size_t o0 = (((size_t)(bb0*HEADS + h)) * SEQ + s0) * HD + d;
                size_t o1 = (((size_t)(bb1*HEADS + h)) * SEQ + s1) * HD + d;
                if (mode == 1) {
                    *reinterpret_cast<float2*>(&out[o0]) = make_float2(va0, va1);
                    *reinterpret_cast<float2*>(&out[o1]) = make_float2(vb0, vb1);
                } else if (mode == 2) {
                    float h0, l0_, h1, l1_;
                    split2(va0, h0, l0_); split2(va1, h1, l1_);
                    *reinterpret_cast<float2*>(&out [o0]) = make_float2(h0, h1);
                    *reinterpret_cast<float2*>(&out2[o0]) = make_float2(l0_, l1_);
                    split2(vb0, h0, l0_); split2(vb1, h1, l1_);
                    *reinterpret_cast<float2*>(&out [o1]) = make_float2(h0, h1);
                    *reinterpret_cast<float2*>(&out2[o1]) = make_float2(l0_, l1_);
                } else { // mode 3: tf32-rounded
                    *reinterpret_cast<float2*>(&out[o0]) =
                        make_float2(__uint_as_float(f2tf(va0)), __uint_as_float(f2tf(va1)));
                    *reinterpret_cast<float2*>(&out[o1]) =
                        make_float2(__uint_as_float(f2tf(vb0)), __uint_as_float(f2tf(vb1)));
                }
            }
        }
    }
}

// ---------------- 3xTF32 flash attention, cp.async double-buffered ----------------
// Block: 128 q-rows of one (b,h), 8 warps x 16 rows. KV tiles of 32. Register softmax.
// K pre-split (Kh,Kl) and V pre-rounded (Vh) by the projection GEMMs -> no conversion here.
// dyn smem (floats):
//   stage s (s=0,1) at s*6656: Kh[32][68] @+0, Kl[32][68] @+2176, Vh[32][72] @+4352
//   PS [128][36] @ 13312 (4608)    total 17920 floats = 71680 B
//   Q stage overlays [128][68] at 0 (8704 floats, used once before the loop)
#define FL_SMEM_BYTES 71680
__global__ __launch_bounds__(256) void flash3x(
    const float* __restrict__ Q, const float* __restrict__ Kh_g,
    const float* __restrict__ Kl_g, const float* __restrict__ Vh_g,
    float* __restrict__ O)
{
    extern __shared__ float dsm[];
    float (*PS)[36] = reinterpret_cast<float(*)[36]>(dsm + 13312);
    float (*QS)[68] = reinterpret_cast<float(*)[68]>(dsm);

    int t = threadIdx.x;
    int lane = t & 31, w = t >> 5;
    int gid = lane >> 2, tig = lane & 3;
    int bh_ = blockIdx.y;
    int q0 = blockIdx.x * 128;
    const float* Qb  = Q    + ((size_t)bh_ * SEQ + q0) * HD;
    const float* Khb = Kh_g + (size_t)bh_ * SEQ * HD;
    const float* Klb = Kl_g + (size_t)bh_ * SEQ * HD;
    const float* Vhb = Vh_g + (size_t)bh_ * SEQ * HD;

    // stage Q (raw fp32), extract hi/lo fragments to registers
    #pragma unroll
    for (int p = 0; p < 8; p++) {
        int idx4 = t + p * 256;
        int row = idx4 >> 4, c4 = idx4 & 15;
        float4 v = *reinterpret_cast<const float4*>(&Qb[(size_t)row*HD + c4*4]);
        *reinterpret_cast<float4*>(&QS[row][c4*4]) = v;
    }
    __syncthreads();
    uint32_t qh[8][4], ql[8][4];
    {
        int r0 = w * 16 + gid;
        #pragma unroll
        for (int kq = 0; kq < 8; kq++) {
            float x0 = QS[r0  ][kq*8+tig  ];
            float x1 = QS[r0+8][kq*8+tig  ];
            float x2 = QS[r0  ][kq*8+tig+4];
            float x3 = QS[r0+8][kq*8+tig+4];
            float h, l;
            split2(x0, h, l); qh[kq][0] = fbits(h); ql[kq][0] = fbits(l);
            split2(x1, h, l); qh[kq][1] = fbits(h); ql[kq][1] = fbits(l);
            split2(x2, h, l); qh[kq][2] = fbits(h); ql[kq][2] = fbits(l);
            split2(x3, h, l); qh[kq][3] = fbits(h); ql[kq][3] = fbits(l);
        }
    }
    __syncthreads();   // Q frags in regs; smem free for K/V staging

    float o[8][4];
    #pragma unroll
    for (int i = 0; i < 8; i++)
        #pragma unroll
        for (int j = 0; j < 4; j++) o[i][j] = 0.0f;
    float m0v = -1e30f, m1v = -1e30f, l0 = 0.0f, l1 = 0.0f;
    const float SCALE = 0.125f;

    // per-thread copy coords: 512 chunks per array (32 rows x 16), 2 per thread per array
    int krow0 = (t      ) >> 4, kc0 = (t      ) & 15;
    int krow1 = (t + 256) >> 4, kc1 = (t + 256) & 15;

    const int NT = SEQ / 32;  // 64 tiles
    // prologue: tile 0 -> stage 0
    {
        float* sKh = dsm; float* sKl = dsm + 2176; float* sVh = dsm + 4352;
        cp16(sKh + krow0*68 + kc0*4, Khb + (size_t)krow0*HD + kc0*4);
        cp16(sKh + krow1*68 + kc1*4, Khb + (size_t)krow1*HD + kc1*4);
        cp16(sKl + krow0*68 + kc0*4, Klb + (size_t)krow0*HD + kc0*4);
        cp16(sKl + krow1*68 + kc1*4, Klb + (size_t)krow1*HD + kc1*4);
        cp16(sVh + krow0*72 + kc0*4, Vhb + (size_t)krow0*HD + kc0*4);
        cp16(sVh + krow1*72 + kc1*4, Vhb + (size_t)krow1*HD + kc1*4);
        cp_commit();
    }

    for (int tt = 0; tt < NT; tt++) {
        if (tt + 1 < NT) {
            int st = (tt + 1) & 1;
            size_t kt = (size_t)(tt + 1) * 32;
            float* sKh = dsm + st*6656; float* sKl = sKh + 2176; float* sVh = sKh + 4352;
            cp16(sKh + krow0*68 + kc0*4, Khb + (kt+krow0)*HD + kc0*4);
            cp16(sKh + krow1*68 + kc1*4, Khb + (kt+krow1)*HD + kc1*4);
            cp16(sKl + krow0*68 + kc0*4, Klb + (kt+krow0)*HD + kc0*4);
            cp16(sKl + krow1*68 + kc1*4, Klb + (kt+krow1)*HD + kc1*4);
            cp16(sVh + krow0*72 + kc0*4, Vhb + (kt+krow0)*HD + kc0*4);
            cp16(sVh + krow1*72 + kc1*4, Vhb + (kt+krow1)*HD + kc1*4);
            cp_commit();
            cp_wait1();
        } else {
            cp_wait0();
        }
        __syncthreads();
        float* sKh = dsm + (tt & 1)*6656;
        float* sKl = sKh + 2176;
        float* sVh = sKh + 4352;

        // S = Q @ K^T  (16 rows x 32 cols per warp), 3xTF32
        float s[4][4];
        #pragma unroll
        for (int nt = 0; nt < 4; nt++)
            #pragma unroll
            for (int r = 0; r < 4; r++) s[nt][r] = 0.0f;
        #pragma unroll
        for (int kq = 0; kq < 8; kq++) {
            uint32_t bhf[4][2], blf[4][2];
            #pragma unroll
            for (int nt = 0; nt < 4; nt++) {
                int nc = nt * 8 + gid;
                bhf[nt][0] = fbits(sKh[nc*68 + kq*8+tig  ]);
                bhf[nt][1] = fbits(sKh[nc*68 + kq*8+tig+4]);
                blf[nt][0] = fbits(sKl[nc*68 + kq*8+tig  ]);
                blf[nt][1] = fbits(sKl[nc*68 + kq*8+tig+4]);
            }
            #pragma unroll
            for (int nt = 0; nt < 4; nt++) {
                mma_tf32(s[nt], qh[kq], bhf[nt]);
                mma_tf32(s[nt], ql[kq], bhf[nt]);
                mma_tf32(s[nt], qh[kq], blf[nt]);
            }
        }

        // register softmax: thread owns rows (w*16+gid) and (+8), 8 cols each
        float tm0 = -1e30f, tm1 = -1e30f;
        #pragma unroll
        for (int nt = 0; nt < 4; nt++) {
            tm0 = fmaxf(tm0, fmaxf(s[nt][0], s[nt][1]));
            tm1 = fmaxf(tm1, fmaxf(s[nt][2], s[nt][3]));
        }
        tm0 *= SCALE; tm1 *= SCALE;
        tm0 = fmaxf(tm0, __shfl_xor_sync(0xffffffffu, tm0, 1));
        tm0 = fmaxf(tm0, __shfl_xor_sync(0xffffffffu, tm0, 2));
        tm1 = fmaxf(tm1, __shfl_xor_sync(0xffffffffu, tm1, 1));
        tm1 = fmaxf(tm1, __shfl_xor_sync(0xffffffffu, tm1, 2));
        float mn0 = fmaxf(m0v, tm0), mn1 = fmaxf(m1v, tm1);
        float a0s = __expf(m0v - mn0), a1s = __expf(m1v - mn1);
        m0v = mn0; m1v = mn1;
        float rs0 = 0.0f, rs1 = 0.0f;
        int prow = w * 16 + gid;
        #pragma unroll
        for (int nt = 0; nt < 4; nt++) {
            float p0 = __expf(s[nt][0]*SCALE - mn0);
            float p1 = __expf(s[nt][1]*SCALE - mn0);
            float p2 = __expf(s[nt][2]*SCALE - mn1);
            float p3 = __expf(s[nt][3]*SCALE - mn1);
            rs0 += p0 + p1; rs1 += p2 + p3;
            int col = nt*8 + tig*2;
            PS[prow  ][col]   = __uint_as_float(f2tf(p0));
            PS[prow  ][col+1] = __uint_as_float(f2tf(p1));
            PS[prow+8][col]   = __uint_as_float(f2tf(p2));
            PS[prow+8][col+1] = __uint_as_float(f2tf(p3));
        }
        rs0 += __shfl_xor_sync(0xffffffffu, rs0, 1);
        rs0 += __shfl_xor_sync(0xffffffffu, rs0, 2);
        rs1 += __shfl_xor_sync(0xffffffffu, rs1, 1);
        rs1 += __shfl_xor_sync(0xffffffffu, rs1, 2);
        l0 = l0 * a0s + rs0;
        l1 = l1 * a1s + rs1;
        #pragma unroll
        for (int nt = 0; nt < 8; nt++) {
            o[nt][0] *= a0s; o[nt][1] *= a0s;
            o[nt][2] *= a1s; o[nt][3] *= a1s;
        }
        __syncwarp();

        // O += P @ V   (P and V single-tf32 -> 1 mma per tile)
        #pragma unroll
        for (int kp = 0; kp < 4; kp++) {
            uint32_t af[4];
            af[0] = fbits(PS[prow  ][kp*8+tig  ]);
            af[1] = fbits(PS[prow+8][kp*8+tig  ]);
            af[2] = fbits(PS[prow  ][kp*8+tig+4]);
            af[3] = fbits(PS[prow+8][kp*8+tig+4]);
            #pragma unroll
            for (int nt = 0; nt < 8; nt++) {
                uint32_t bv2[2];
                bv2[0] = fbits(sVh[(kp*8+tig  )*72 + nt*8+gid]);
                bv2[1] = fbits(sVh[(kp*8+tig+4)*72 + nt*8+gid]);
                mma_tf32(o[nt], af, bv2);
            }
        }
        __syncthreads();   // all warps done reading this stage before it is refilled
    }

    // epilogue -> O in (b,s,e) layout
    float inv0 = 1.0f / l0, inv1 = 1.0f / l1;
    int b = bh_ >> 4, h = bh_ & 15;
    int grow = q0 + w * 16 + gid;
    #pragma unroll
    for (int nt = 0; nt < 8; nt++) {
        int col = h*HD + nt*8 + tig*2;
        float2 v0 = make_float2(o[nt][0]*inv0, o[nt][1]*inv0);
        float2 v1 = make_float2(o[nt][2]*inv1, o[nt][3]*inv1);
        *reinterpret_cast<float2*>(&O[((size_t)(b*SEQ + grow)) * EMB + col]) = v0;
        *reinterpret_cast<float2*>(&O[((size_t)(b*SEQ + grow + 8)) * EMB + col]) = v1;
    }
}

// ---------------- launch ----------------
extern "C" void kernel_launch(void* const* d_in, const int* in_sizes, int n_in,
                              void* d_out, int out_size)
{
    const float* query   = (const float*)d_in[0];
    const float* key     = (const float*)d_in[1];
    const float* value   = (const float*)d_in[2];
    const float* wq      = (const float*)d_in[3];
    const float* bq      = (const float*)d_in[4];
    const float* wk      = (const float*)d_in[5];
    const float* bk      = (const float*)d_in[6];
    const float* wv      = (const float*)d_in[7];
    const float* bv      = (const float*)d_in[8];
    const float* wo      = (const float*)d_in[9];
    const float* bo      = (const float*)d_in[10];
    const float* q_theta = (const float*)d_in[11];
    const float* q_phi   = (const float*)d_in[12];
    const float* q_preW  = (const float*)d_in[13];
    const float* q_preb  = (const float*)d_in[14];
    const float* q_postW = (const float*)d_in[15];
    const float* q_postb = (const float*)d_in[16];
    const float* k_theta = (const float*)d_in[17];
    const float* k_phi   = (const float*)d_in[18];
    const float* k_preW  = (const float*)d_in[19];
    const float* k_preb  = (const float*)d_in[20];
    const float* k_postW = (const float*)d_in[21];
    const float* k_postb = (const float*)d_in[22];

    static float *Q = nullptr, *Kh, *Kl, *Vh, *O, *Wq, *Wk, *Mq, *Mk, *beq, *bek, *bqf, *bkf;
    if (!Q) {
        cudaGetSymbolAddress((void**)&Q,  g_Q);
        cudaGetSymbolAddress((void**)&Kh, g_Kh);
        cudaGetSymbolAddress((void**)&Kl, g_Kl);
        cudaGetSymbolAddress((void**)&Vh, g_Vh);
        cudaGetSymbolAddress((void**)&O,  g_O);
        cudaGetSymbolAddress((void**)&Wq, g_Wq);
        cudaGetSymbolAddress((void**)&Wk, g_Wk);
        cudaGetSymbolAddress((void**)&Mq, g_Mq);
        cudaGetSymbolAddress((void**)&Mk, g_Mk);
        cudaGetSymbolAddress((void**)&beq, g_beq);
        cudaGetSymbolAddress((void**)&bek, g_bek);
        cudaGetSymbolAddress((void**)&bqf, g_bqf);
        cudaGetSymbolAddress((void**)&bkf, g_bkf);
        cudaFuncSetAttribute(flash3x, cudaFuncAttributeMaxDynamicSharedMemorySize, FL_SMEM_BYTES);
    }

    // 1) fold the quantum layer into effective projection weights/biases
    quantum_compose<<<1, 256>>>(q_theta, q_phi, q_preW, q_preb, q_postW, q_postb, Mq, beq);
    quantum_compose<<<1, 256>>>(k_theta, k_phi, k_preW, k_preb, k_postW, k_postb, Mk, bek);
    make_weff<<<dim3(4, EMB), 256>>>(Mq, wq, Wq);
    make_weff<<<dim3(4, EMB), 256>>>(Mk, wk, Wk);
    make_beff<<<4, 256>>>(Mq, beq, bq, bqf);
    make_beff<<<4, 256>>>(Mk, bek, bk, bkf);

    // 2) projections -> (b,h,s,d); K written split hi/lo, V written tf32-rounded
    dim3 gg(EMB / BN, NTOK / BM);
    gemm3x<<<gg, 256>>>(query, Wq, bqf, Q,  nullptr, 1);
    gemm3x<<<gg, 256>>>(key,   Wk, bkf, Kh, Kl,      2);
    gemm3x<<<gg, 256>>>(value, wv, bv,  Vh, nullptr, 3);

    // 3) attention -> (b,s,e)
    flash3x<<<dim3(SEQ / 128, BH), 256, FL_SMEM_BYTES>>>(Q, Kh, Kl, Vh, O);

    // 4) output projection
    gemm3x<<<gg, 256>>>(O, wo, bo, (float*)d_out, nullptr, 0);
}

// round 8
// speedup vs baseline: 2.7235x; 1.3025x over previous
#include <cuda_runtime.h>
#include <math.h>
#include <stdint.h>

// Problem constants
#define BATCH 4
#define SEQ   2048
#define EMB   1024
#define HEADS 16
#define HD    64
#define NTOK  (BATCH*SEQ)     // 8192
#define BH    (BATCH*HEADS)   // 64
#define NQUBITS 6

// ---------------- scratch (static device globals; no allocation) ----------------
__device__ float g_Q[BH*SEQ*HD];       // (b,h,s,d) raw fp32
__device__ float g_Kh[BH*SEQ*HD];      // tf32-rounded K
__device__ float g_Vh[BH*SEQ*HD];      // tf32-rounded V
__device__ float g_O[NTOK*EMB];        // (b,s,e)
__device__ float g_Wq[EMB*EMB];
__device__ float g_Wk[EMB*EMB];
__device__ float g_Mq[HD*HD];
__device__ float g_Mk[HD*HD];
__device__ float g_beq[HD];
__device__ float g_bek[HD];
__device__ float g_bqf[EMB];
__device__ float g_bkf[EMB];

// ---------------- tf32 / cp.async helpers ----------------
__device__ __forceinline__ uint32_t f2tf(float x) {
    uint32_t u; asm("cvt.rna.tf32.f32 %0, %1;" : "=r"(u) : "f"(x)); return u;
}
__device__ __forceinline__ void split2(float x, float& h, float& l) {
    h = __uint_as_float(f2tf(x));
    l = __uint_as_float(f2tf(x - h));
}
__device__ __forceinline__ void mma_tf32(float* d, const uint32_t* a, const uint32_t* b) {
    asm volatile("mma.sync.aligned.m16n8k8.row.col.f32.tf32.tf32.f32 "
        "{%0,%1,%2,%3}, {%4,%5,%6,%7}, {%8,%9}, {%0,%1,%2,%3};"
        : "+f"(d[0]), "+f"(d[1]), "+f"(d[2]), "+f"(d[3])
        : "r"(a[0]), "r"(a[1]), "r"(a[2]), "r"(a[3]), "r"(b[0]), "r"(b[1]));
}
__device__ __forceinline__ uint32_t fbits(float x) { return __float_as_uint(x); }
__device__ __forceinline__ void cp16(void* s, const void* g) {
    asm volatile("cp.async.cg.shared.global [%0], [%1], 16;"
        :: "r"((uint32_t)__cvta_generic_to_shared(s)), "l"(g));
}
__device__ __forceinline__ void cp_commit() { asm volatile("cp.async.commit_group;"); }
__device__ __forceinline__ void cp_wait1() { asm volatile("cp.async.wait_group 1;"); }
__device__ __forceinline__ void cp_wait0() { asm volatile("cp.async.wait_group 0;"); }

// ---------------- quantum layer composition (fp32-exact) ----------------
__global__ __launch_bounds__(256) void quantum_compose(
    const float* __restrict__ theta, const float* __restrict__ phi,
    const float* __restrict__ preW, const float* __restrict__ preb,
    const float* __restrict__ postW, const float* __restrict__ postb,
    float* __restrict__ Meff, float* __restrict__ beff)
{
    __shared__ float A[HD][HD+1];
    __shared__ float bv[HD];
    int t = threadIdx.x;
    for (int idx = t; idx < HD*HD; idx += 256) A[idx >> 6][idx & 63] = preW[idx];
    if (t < HD) bv[t] = preb[t];
    __syncthreads();
    for (int i = 0; i < NQUBITS; i++) {
        float th = theta[i], ph = phi[i];
        float c = cosf(th), s = sinf(th), cp = cosf(ph);
        for (int w = t; w < 32*HD; w += 256) {
            int p = w >> 6, col = w & 63;
            int low = p & ((1 << i) - 1);
            int i0 = ((p >> i) << (i + 1)) | low;
            int i1 = i0 | (1 << i);
            float x0 = A[i0][col], x1 = A[i1][col];
            A[i0][col] = c * x0 - s * x1;
            A[i1][col] = cp * (s * x0 + c * x1);
        }
        if (t < 32) {
            int p = t;
            int low = p & ((1 << i) - 1);
            int i0 = ((p >> i) << (i + 1)) | low;
            int i1 = i0 | (1 << i);
            float x0 = bv[i0], x1 = bv[i1];
            bv[i0] = c * x0 - s * x1;
            bv[i1] = cp * (s * x0 + c * x1);
        }
        __syncthreads();
    }
    for (int idx = t; idx < HD*HD; idx += 256) {
        int i = idx >> 6, j = idx & 63;
        float acc = (i == j) ? 1.0f : 0.0f;
        #pragma unroll 8
        for (int d = 0; d < HD; d++) acc += postW[i*HD + d] * A[d][j];
        Meff[idx] = acc;
    }
    if (t < HD) {
        float acc = postb[t];
        #pragma unroll 8
        for (int d = 0; d < HD; d++) acc += postW[t*HD + d] * bv[d];
        beff[t] = acc;
    }
}

__global__ __launch_bounds__(256) void make_weff(
    const float* __restrict__ M, const float* __restrict__ w, float* __restrict__ weff)
{
    int r = blockIdx.y;
    int j = blockIdx.x * 256 + threadIdx.x;
    int h = r >> 6, i = r & 63;
    __shared__ float Mrow[HD];
    if (threadIdx.x < HD) Mrow[threadIdx.x] = M[i*HD + threadIdx.x];
    __syncthreads();
    float acc = 0.0f;
    #pragma unroll 8
    for (int d = 0; d < HD; d++) acc += Mrow[d] * w[(h*HD + d) * EMB + j];
    weff[(size_t)r * EMB + j] = acc;
}

__global__ __launch_bounds__(256) void make_beff(
    const float* __restrict__ M, const float* __restrict__ beff,
    const float* __restrict__ b_in, float* __restrict__ bfull)
{
    int r = blockIdx.x * 256 + threadIdx.x;
    int h = r >> 6, i = r & 63;
    float acc = beff[i];
    #pragma unroll 8
    for (int d = 0; d < HD; d++) acc += M[i*HD + d] * b_in[h*HD + d];
    bfull[r] = acc;
}

// ---------------- 2xTF32 tensor-core GEMM, cp.async double-buffered ----------------
// C(8192x1024) = X @ W^T + bias. BM=BN=128, BK=16, 8 warps (2x4), warp tile 64x32.
// A split hi/lo at frag build, B tf32-rounded at frag build: D = ah*bh + al*bh.
// mode: 0 = flat raw (m,n); 1 = qkv scatter raw; 3 = qkv scatter tf32-rounded.
#define BM 128
#define BN 128
#define BK 16
#define BKP 20   // pad: frag reads land on distinct banks mod 32
__global__ __launch_bounds__(256) void gemm2x(
    const float* __restrict__ X, const float* __restrict__ W,
    const float* __restrict__ bias, float* __restrict__ out, int mode)
{
    __shared__ float sm[2 * 2 * BM * BKP];   // 2 stages x (A + B) x 128x20 = 40KB
    int t = threadIdx.x;
    int lane = t & 31, w = t >> 5;
    int gid = lane >> 2, tig = lane & 3;
    int wm = w >> 2, wn = w & 3;           // 2 x 4 warp grid
    int m0 = blockIdx.y * BM, n0 = blockIdx.x * BN;

    float acc[4][4][4];
    #pragma unroll
    for (int i = 0; i < 4; i++)
        #pragma unroll
        for (int j = 0; j < 4; j++)
            #pragma unroll
            for (int r = 0; r < 4; r++) acc[i][j][r] = 0.0f;

    // per-thread copy coordinates (A: 512 chunks, B: 512 chunks, 4 per thread)
    int crow0 = (t      ) >> 2, cc0 = (t      ) & 3;
    int crow1 = (t + 256) >> 2, cc1 = (t + 256) & 3;

    const int NSLAB = EMB / BK;  // 64
    // prologue: slab 0 -> stage 0
    {
        float* dA = sm; float* dB = sm + BM*BKP;
        cp16(dA + crow0*BKP + cc0*4, X + (size_t)(m0+crow0)*EMB + cc0*4);
        cp16(dA + crow1*BKP + cc1*4, X + (size_t)(m0+crow1)*EMB + cc1*4);
        cp16(dB + crow0*BKP + cc0*4, W + (size_t)(n0+crow0)*EMB + cc0*4);
        cp16(dB + crow1*BKP + cc1*4, W + (size_t)(n0+crow1)*EMB + cc1*4);
        cp_commit();
    }

    for (int s = 0; s < NSLAB; s++) {
        if (s + 1 < NSLAB) {
            int st = (s + 1) & 1;
            int kk = (s + 1) * BK;
            float* dA = sm + st * 2 * BM * BKP;
            float* dB = dA + BM * BKP;
            cp16(dA + crow0*BKP + cc0*4, X + (size_t)(m0+crow0)*EMB + kk + cc0*4);
            cp16(dA + crow1*BKP + cc1*4, X + (size_t)(m0+crow1)*EMB + kk + cc1*4);
            cp16(dB + crow0*BKP + cc0*4, W + (size_t)(n0+crow0)*EMB + kk + cc0*4);
            cp16(dB + crow1*BKP + cc1*4, W + (size_t)(n0+crow1)*EMB + kk + cc1*4);
            cp_commit();
            cp_wait1();
        } else {
            cp_wait0();
        }
        __syncthreads();
        float* dA = sm + (s & 1) * 2 * BM * BKP;
        float* dB = dA + BM * BKP;
        #pragma unroll
        for (int ks = 0; ks < 2; ks++) {
            int kb = ks * 8;
            uint32_t ah[4][4], al[4][4];
            #pragma unroll
            for (int mt = 0; mt < 4; mt++) {
                int mr = wm*64 + mt*16;
                float h, l;
                split2(dA[(mr+gid  )*BKP + kb+tig  ], h, l); ah[mt][0]=fbits(h); al[mt][0]=fbits(l);
                split2(dA[(mr+gid+8)*BKP + kb+tig  ], h, l); ah[mt][1]=fbits(h); al[mt][1]=fbits(l);
                split2(dA[(mr+gid  )*BKP + kb+tig+4], h, l); ah[mt][2]=fbits(h); al[mt][2]=fbits(l);
                split2(dA[(mr+gid+8)*BKP + kb+tig+4], h, l); ah[mt][3]=fbits(h); al[mt][3]=fbits(l);
            }
            uint32_t bh[4][2];
            #pragma unroll
            for (int nt = 0; nt < 4; nt++) {
                int nc = wn*32 + nt*8;
                bh[nt][0] = f2tf(dB[(nc+gid)*BKP + kb+tig  ]);
                bh[nt][1] = f2tf(dB[(nc+gid)*BKP + kb+tig+4]);
            }
            #pragma unroll
            for (int mt = 0; mt < 4; mt++)
                #pragma unroll
                for (int nt = 0; nt < 4; nt++) {
                    mma_tf32(acc[mt][nt], ah[mt], bh[nt]);
                    mma_tf32(acc[mt][nt], al[mt], bh[nt]);
                }
        }
        __syncthreads();
    }

    // epilogue
    #pragma unroll
    for (int mt = 0; mt < 4; mt++) {
        int m = m0 + wm*64 + mt*16 + gid;
        #pragma unroll
        for (int nt = 0; nt < 4; nt++) {
            int n = n0 + wn*32 + nt*8 + tig*2;
            float b0 = bias[n], b1 = bias[n+1];
            float va0 = acc[mt][nt][0] + b0, va1 = acc[mt][nt][1] + b1;
            float vb0 = acc[mt][nt][2] + b0, vb1 = acc[mt][nt][3] + b1;
            if (mode == 0) {
                *reinterpret_cast<float2*>(&out[(size_t)m * EMB + n]) = make_float2(va0, va1);
                *reinterpret_cast<float2*>(&out[(size_t)(m+8) * EMB + n]) = make_float2(vb0, vb1);
            } else {
                int h = n >> 6, d = n & 63;
                int bb0 = m >> 11, s0 = m & 2047;
                int m1 = m + 8;
                int bb1 = m1 >> 11, s1 = m1 & 2047;
                size_t o0 = (((size_t)(bb0*HEADS + h)) * SEQ + s0) * HD + d;
                size_t o1 = (((size_t)(bb1*HEADS + h)) * SEQ + s1) * HD + d;
                if (mode == 1) {
                    *reinterpret_cast<float2*>(&out[o0]) = make_float2(va0, va1);
                    *reinterpret_cast<float2*>(&out[o1]) = make_float2(vb0, vb1);
                } else { // mode 3: tf32-rounded
                    *reinterpret_cast<float2*>(&out[o0]) =
                        make_float2(__uint_as_float(f2tf(va0)), __uint_as_float(f2tf(va1)));
                    *reinterpret_cast<float2*>(&out[o1]) =
                        make_float2(__uint_as_float(f2tf(vb0)), __uint_as_float(f2tf(vb1)));
                }
            }
        }
    }
}

// ---------------- 2xTF32 flash attention, cp.async double-buffered ----------------
// Block: 128 q-rows of one (b,h), 8 warps x 16 rows. KV tiles of 32. Register softmax.
// K and V pre-rounded to tf32 by their projection GEMMs. Q split hi/lo in registers.
// QK: 2 mma (qh*k + ql*k). PV: 1 mma (tf32 P * tf32 V).
// dyn smem (floats):
//   stage s (s=0,1) at s*4480: Kh[32][68] @+0 (2176), Vh[32][72] @+2176 (2304)
//   PS [128][36] @ 8960 (4608)    total 13568 floats = 54272 B
//   Q stage overlays [128][68] at 0 (8704 floats, used once before the loop)
#define FL_SMEM_BYTES 54272
__global__ __launch_bounds__(256) void flash2x(
    const float* __restrict__ Q, const float* __restrict__ Kh_g,
    const float* __restrict__ Vh_g, float* __restrict__ O)
{
    extern __shared__ float dsm[];
    float (*PS)[36] = reinterpret_cast<float(*)[36]>(dsm + 8960);
    float (*QS)[68] = reinterpret_cast<float(*)[68]>(dsm);

    int t = threadIdx.x;
    int lane = t & 31, w = t >> 5;
    int gid = lane >> 2, tig = lane & 3;
    int bh_ = blockIdx.y;
    int q0 = blockIdx.x * 128;
    const float* Qb  = Q    + ((size_t)bh_ * SEQ + q0) * HD;
    const float* Khb = Kh_g + (size_t)bh_ * SEQ * HD;
    const float* Vhb = Vh_g + (size_t)bh_ * SEQ * HD;

    // stage Q (raw fp32), extract hi/lo fragments to registers
    #pragma unroll
    for (int p = 0; p < 8; p++) {
        int idx4 = t + p * 256;
        int row = idx4 >> 4, c4 = idx4 & 15;
        float4 v = *reinterpret_cast<const float4*>(&Qb[(size_t)row*HD + c4*4]);
        *reinterpret_cast<float4*>(&QS[row][c4*4]) = v;
    }
    __syncthreads();
    uint32_t qh[8][4], ql[8][4];
    {
        int r0 = w * 16 + gid;
        #pragma unroll
        for (int kq = 0; kq < 8; kq++) {
            float x0 = QS[r0  ][kq*8+tig  ];
            float x1 = QS[r0+8][kq*8+tig  ];
            float x2 = QS[r0  ][kq*8+tig+4];
            float x3 = QS[r0+8][kq*8+tig+4];
            float h, l;
            split2(x0, h, l); qh[kq][0] = fbits(h); ql[kq][0] = fbits(l);
            split2(x1, h, l); qh[kq][1] = fbits(h); ql[kq][1] = fbits(l);
            split2(x2, h, l); qh[kq][2] = fbits(h); ql[kq][2] = fbits(l);
            split2(x3, h, l); qh[kq][3] = fbits(h); ql[kq][3] = fbits(l);
        }
    }
    __syncthreads();   // Q frags in regs; smem free for K/V staging

    float o[8][4];
    #pragma unroll
    for (int i = 0; i < 8; i++)
        #pragma unroll
        for (int j = 0; j < 4; j++) o[i][j] = 0.0f;
    float m0v = -1e30f, m1v = -1e30f, l0 = 0.0f, l1 = 0.0f;
    const float SCALE = 0.125f;

    // per-thread copy coords: 512 chunks per array (32 rows x 16), 2 per thread per array
    int krow0 = (t      ) >> 4, kc0 = (t      ) & 15;
    int krow1 = (t + 256) >> 4, kc1 = (t + 256) & 15;

    const int NT = SEQ / 32;  // 64 tiles
    // prologue: tile 0 -> stage 0
    {
        float* sKh = dsm; float* sVh = dsm + 2176;
        cp16(sKh + krow0*68 + kc0*4, Khb + (size_t)krow0*HD + kc0*4);
        cp16(sKh + krow1*68 + kc1*4, Khb + (size_t)krow1*HD + kc1*4);
        cp16(sVh + krow0*72 + kc0*4, Vhb + (size_t)krow0*HD + kc0*4);
        cp16(sVh + krow1*72 + kc1*4, Vhb + (size_t)krow1*HD + kc1*4);
        cp_commit();
    }

    for (int tt = 0; tt < NT; tt++) {
        if (tt + 1 < NT) {
            int st = (tt + 1) & 1;
            size_t kt = (size_t)(tt + 1) * 32;
            float* sKh = dsm + st*4480; float* sVh = sKh + 2176;
            cp16(sKh + krow0*68 + kc0*4, Khb + (kt+krow0)*HD + kc0*4);
            cp16(sKh + krow1*68 + kc1*4, Khb + (kt+krow1)*HD + kc1*4);
            cp16(sVh + krow0*72 + kc0*4, Vhb + (kt+krow0)*HD + kc0*4);
            cp16(sVh + krow1*72 + kc1*4, Vhb + (kt+krow1)*HD + kc1*4);
            cp_commit();
            cp_wait1();
        } else {
            cp_wait0();
        }
        __syncthreads();
        float* sKh = dsm + (tt & 1)*4480;
        float* sVh = sKh + 2176;

        // S = Q @ K^T  (16 rows x 32 cols per warp), 2xTF32
        float s[4][4];
        #pragma unroll
        for (int nt = 0; nt < 4; nt++)
            #pragma unroll
            for (int r = 0; r < 4; r++) s[nt][r] = 0.0f;
        #pragma unroll
        for (int kq = 0; kq < 8; kq++) {
            uint32_t bhf[4][2];
            #pragma unroll
            for (int nt = 0; nt < 4; nt++) {
                int nc = nt * 8 + gid;
                bhf[nt][0] = fbits(sKh[nc*68 + kq*8+tig  ]);
                bhf[nt][1] = fbits(sKh[nc*68 + kq*8+tig+4]);
            }
            #pragma unroll
            for (int nt = 0; nt < 4; nt++) {
                mma_tf32(s[nt], qh[kq], bhf[nt]);
                mma_tf32(s[nt], ql[kq], bhf[nt]);
            }
        }

        // register softmax: thread owns rows (w*16+gid) and (+8), 8 cols each
        float tm0 = -1e30f, tm1 = -1e30f;
        #pragma unroll
        for (int nt = 0; nt < 4; nt++) {
            tm0 = fmaxf(tm0, fmaxf(s[nt][0], s[nt][1]));
            tm1 = fmaxf(tm1, fmaxf(s[nt][2], s[nt][3]));
        }
        tm0 *= SCALE; tm1 *= SCALE;
        tm0 = fmaxf(tm0, __shfl_xor_sync(0xffffffffu, tm0, 1));
        tm0 = fmaxf(tm0, __shfl_xor_sync(0xffffffffu, tm0, 2));
        tm1 = fmaxf(tm1, __shfl_xor_sync(0xffffffffu, tm1, 1));
        tm1 = fmaxf(tm1, __shfl_xor_sync(0xffffffffu, tm1, 2));
        float mn0 = fmaxf(m0v, tm0), mn1 = fmaxf(m1v, tm1);
        float a0s = __expf(m0v - mn0), a1s = __expf(m1v - mn1);
        m0v = mn0; m1v = mn1;
        float rs0 = 0.0f, rs1 = 0.0f;
        int prow = w * 16 + gid;
        #pragma unroll
        for (int nt = 0; nt < 4; nt++) {
            float p0 = __expf(s[nt][0]*SCALE - mn0);
            float p1 = __expf(s[nt][1]*SCALE - mn0);
            float p2 = __expf(s[nt][2]*SCALE - mn1);
            float p3 = __expf(s[nt][3]*SCALE - mn1);
            rs0 += p0 + p1; rs1 += p2 + p3;
            int col = nt*8 + tig*2;
            PS[prow  ][col]   = __uint_as_float(f2tf(p0));
            PS[prow  ][col+1] = __uint_as_float(f2tf(p1));
            PS[prow+8][col]   = __uint_as_float(f2tf(p2));
            PS[prow+8][col+1] = __uint_as_float(f2tf(p3));
        }
        rs0 += __shfl_xor_sync(0xffffffffu, rs0, 1);
        rs0 += __shfl_xor_sync(0xffffffffu, rs0, 2);
        rs1 += __shfl_xor_sync(0xffffffffu, rs1, 1);
        rs1 += __shfl_xor_sync(0xffffffffu, rs1, 2);
        l0 = l0 * a0s + rs0;
        l1 = l1 * a1s + rs1;
        #pragma unroll
        for (int nt = 0; nt < 8; nt++) {
            o[nt][0] *= a0s; o[nt][1] *= a0s;
            o[nt][2] *= a1s; o[nt][3] *= a1s;
        }
        __syncwarp();

        // O += P @ V   (P and V single-tf32 -> 1 mma per tile)
        #pragma unroll
        for (int kp = 0; kp < 4; kp++) {
            uint32_t af[4];
            af[0] = fbits(PS[prow  ][kp*8+tig  ]);
            af[1] = fbits(PS[prow+8][kp*8+tig  ]);
            af[2] = fbits(PS[prow  ][kp*8+tig+4]);
            af[3] = fbits(PS[prow+8][kp*8+tig+4]);
            #pragma unroll
            for (int nt = 0; nt < 8; nt++) {
                uint32_t bv2[2];
                bv2[0] = fbits(sVh[(kp*8+tig  )*72 + nt*8+gid]);
                bv2[1] = fbits(sVh[(kp*8+tig+4)*72 + nt*8+gid]);
                mma_tf32(o[nt], af, bv2);
            }
        }
        __syncthreads();   // all warps done reading this stage before it is refilled
    }

    // epilogue -> O in (b,s,e) layout
    float inv0 = 1.0f / l0, inv1 = 1.0f / l1;
    int b = bh_ >> 4, h = bh_ & 15;
    int grow = q0 + w * 16 + gid;
    #pragma unroll
    for (int nt = 0; nt < 8; nt++) {
        int col = h*HD + nt*8 + tig*2;
        float2 v0 = make_float2(o[nt][0]*inv0, o[nt][1]*inv0);
        float2 v1 = make_float2(o[nt][2]*inv1, o[nt][3]*inv1);
        *reinterpret_cast<float2*>(&O[((size_t)(b*SEQ + grow)) * EMB + col]) = v0;
        *reinterpret_cast<float2*>(&O[((size_t)(b*SEQ + grow + 8)) * EMB + col]) = v1;
    }
}

// ---------------- launch ----------------
extern "C" void kernel_launch(void* const* d_in, const int* in_sizes, int n_in,
                              void* d_out, int out_size)
{
    const float* query   = (const float*)d_in[0];
    const float* key     = (const float*)d_in[1];
    const float* value   = (const float*)d_in[2];
    const float* wq      = (const float*)d_in[3];
    const float* bq      = (const float*)d_in[4];
    const float* wk      = (const float*)d_in[5];
    const float* bk      = (const float*)d_in[6];
    const float* wv      = (const float*)d_in[7];
    const float* bv      = (const float*)d_in[8];
    const float* wo      = (const float*)d_in[9];
    const float* bo      = (const float*)d_in[10];
    const float* q_theta = (const float*)d_in[11];
    const float* q_phi   = (const float*)d_in[12];
    const float* q_preW  = (const float*)d_in[13];
    const float* q_preb  = (const float*)d_in[14];
    const float* q_postW = (const float*)d_in[15];
    const float* q_postb = (const float*)d_in[16];
    const float* k_theta = (const float*)d_in[17];
    const float* k_phi   = (const float*)d_in[18];
    const float* k_preW  = (const float*)d_in[19];
    const float* k_preb  = (const float*)d_in[20];
    const float* k_postW = (const float*)d_in[21];
    const float* k_postb = (const float*)d_in[22];

    static float *Q = nullptr, *Kh, *Vh, *O, *Wq, *Wk, *Mq, *Mk, *beq, *bek, *bqf, *bkf;
    if (!Q) {
        cudaGetSymbolAddress((void**)&Q,  g_Q);
        cudaGetSymbolAddress((void**)&Kh, g_Kh);
        cudaGetSymbolAddress((void**)&Vh, g_Vh);
        cudaGetSymbolAddress((void**)&O,  g_O);
        cudaGetSymbolAddress((void**)&Wq, g_Wq);
        cudaGetSymbolAddress((void**)&Wk, g_Wk);
        cudaGetSymbolAddress((void**)&Mq, g_Mq);
        cudaGetSymbolAddress((void**)&Mk, g_Mk);
        cudaGetSymbolAddress((void**)&beq, g_beq);
        cudaGetSymbolAddress((void**)&bek, g_bek);
        cudaGetSymbolAddress((void**)&bqf, g_bqf);
        cudaGetSymbolAddress((void**)&bkf, g_bkf);
        cudaFuncSetAttribute(flash2x, cudaFuncAttributeMaxDynamicSharedMemorySize, FL_SMEM_BYTES);
    }

    // 1) fold the quantum layer into effective projection weights/biases
    quantum_compose<<<1, 256>>>(q_theta, q_phi, q_preW, q_preb, q_postW, q_postb, Mq, beq);
    quantum_compose<<<1, 256>>>(k_theta, k_phi, k_preW, k_preb, k_postW, k_postb, Mk, bek);
    make_weff<<<dim3(4, EMB), 256>>>(Mq, wq, Wq);
    make_weff<<<dim3(4, EMB), 256>>>(Mk, wk, Wk);
    make_beff<<<4, 256>>>(Mq, beq, bq, bqf);
    make_beff<<<4, 256>>>(Mk, bek, bk, bkf);

    // 2) projections -> (b,h,s,d); K and V written tf32-rounded
    dim3 gg(EMB / BN, NTOK / BM);
    gemm2x<<<gg, 256>>>(query, Wq, bqf, Q,  1);
    gemm2x<<<gg, 256>>>(key,   Wk, bkf, Kh, 3);
    gemm2x<<<gg, 256>>>(value, wv, bv,  Vh, 3);

    // 3) attention -> (b,s,e)
    flash2x<<<dim3(SEQ / 128, BH), 256, FL_SMEM_BYTES>>>(Q, Kh, Vh, O);

    // 4) output projection
    gemm2x<<<gg, 256>>>(O, wo, bo, (float*)d_out, 0);
}

// round 11
// speedup vs baseline: 3.2700x; 1.2007x over previous
#include <cuda_runtime.h>
#include <cuda_bf16.h>
#include <math.h>
#include <stdint.h>

// Problem constants
#define BATCH 4
#define SEQ   2048
#define EMB   1024
#define HEADS 16
#define HD    64
#define NTOK  (BATCH*SEQ)     // 8192
#define BH    (BATCH*HEADS)   // 64
#define NQUBITS 6
#define PLA   4194304u        // NTOK*EMB/2 = plane stride (u32) for activations (== BH*SEQ*HD/2)
#define PLB   524288u         // EMB*EMB/2  = plane stride (u32) for weights

// ---------------- scratch (static device globals; no allocation) ----------------
__device__ uint32_t g_Xq[2*PLA];   // query input, bf16x2 planes [2][8192][512]
__device__ uint32_t g_Xk[2*PLA];
__device__ uint32_t g_Xv[2*PLA];
__device__ uint32_t g_Op[2*PLA];   // attention output, bf16x2 planes (b,s,e)
__device__ uint32_t g_Qp[2*PLA];   // Q bf16x2 planes (b,h,s,d-pairs)
__device__ uint32_t g_Kp[2*PLA];   // K bf16x2 planes
__device__ float    g_Vh[BH*SEQ*HD]; // V tf32-rounded fp32 (b,h,s,d)
__device__ uint32_t g_Wqp[2*PLB];  // effective Q weight, bf16x2 planes [2][1024][512]
__device__ uint32_t g_Wkp[2*PLB];
__device__ uint32_t g_Wvp[2*PLB];
__device__ uint32_t g_Wop[2*PLB];
__device__ float g_Mq[HD*HD];
__device__ float g_Mk[HD*HD];
__device__ float g_beq[HD];
__device__ float g_bek[HD];
__device__ float g_bqf[EMB];
__device__ float g_bkf[EMB];

// ---------------- helpers ----------------
__device__ __forceinline__ uint32_t f2tf(float x) {
    uint32_t u; asm("cvt.rna.tf32.f32 %0, %1;" : "=r"(u) : "f"(x)); return u;
}
__device__ __forceinline__ uint32_t fbits(float x) { return __float_as_uint(x); }
__device__ __forceinline__ void mma_tf32(float* d, const uint32_t* a, const uint32_t* b) {
    asm volatile("mma.sync.aligned.m16n8k8.row.col.f32.tf32.tf32.f32 "
        "{%0,%1,%2,%3}, {%4,%5,%6,%7}, {%8,%9}, {%0,%1,%2,%3};"
        : "+f"(d[0]), "+f"(d[1]), "+f"(d[2]), "+f"(d[3])
        : "r"(a[0]), "r"(a[1]), "r"(a[2]), "r"(a[3]), "r"(b[0]), "r"(b[1]));
}
__device__ __forceinline__ void mma_bf16(float* d, const uint32_t* a, const uint32_t* b) {
    asm volatile("mma.sync.aligned.m16n8k16.row.col.f32.bf16.bf16.f32 "
        "{%0,%1,%2,%3}, {%4,%5,%6,%7}, {%8,%9}, {%0,%1,%2,%3};"
        : "+f"(d[0]), "+f"(d[1]), "+f"(d[2]), "+f"(d[3])
        : "r"(a[0]), "r"(a[1]), "r"(a[2]), "r"(a[3]), "r"(b[0]), "r"(b[1]));
}
// split a float pair into bf16x2 hi plane + bf16x2 lo (residual) plane
__device__ __forceinline__ void pack2(float x, float y, uint32_t* hi, uint32_t* lo) {
    __nv_bfloat162 h = __float22bfloat162_rn(make_float2(x, y));
    float2 hf = __bfloat1622float2(h);
    __nv_bfloat162 l = __float22bfloat162_rn(make_float2(x - hf.x, y - hf.y));
    *hi = *reinterpret_cast<uint32_t*>(&h);
    *lo = *reinterpret_cast<uint32_t*>(&l);
}
__device__ __forceinline__ void cp16(void* s, const void* g) {
    asm volatile("cp.async.cg.shared.global [%0], [%1], 16;"
        :: "r"((uint32_t)__cvta_generic_to_shared(s)), "l"(g));
}
__device__ __forceinline__ void cp_commit() { asm volatile("cp.async.commit_group;"); }
__device__ __forceinline__ void cp_wait1() { asm volatile("cp.async.wait_group 1;"); }
__device__ __forceinline__ void cp_wait0() { asm volatile("cp.async.wait_group 0;"); }

// ---------------- quantum layer composition (fp32-exact) ----------------
__global__ __launch_bounds__(256) void quantum_compose(
    const float* __restrict__ theta, const float* __restrict__ phi,
    const float* __restrict__ preW, const float* __restrict__ preb,
    const float* __restrict__ postW, const float* __restrict__ postb,
    float* __restrict__ Meff, float* __restrict__ beff)
{
    __shared__ float A[HD][HD+1];
    __shared__ float bv[HD];
    int t = threadIdx.x;
    for (int idx = t; idx < HD*HD; idx += 256) A[idx >> 6][idx & 63] = preW[idx];
    if (t < HD) bv[t] = preb[t];
    __syncthreads();
    for (int i = 0; i < NQUBITS; i++) {
        float th = theta[i], ph = phi[i];
        float c = cosf(th), s = sinf(th), cp = cosf(ph);
        for (int w = t; w < 32*HD; w += 256) {
            int p = w >> 6, col = w & 63;
            int low = p & ((1 << i) - 1);
            int i0 = ((p >> i) << (i + 1)) | low;
            int i1 = i0 | (1 << i);
            float x0 = A[i0][col], x1 = A[i1][col];
            A[i0][col] = c * x0 - s * x1;
            A[i1][col] = cp * (s * x0 + c * x1);
        }
        if (t < 32) {
            int p = t;
            int low = p & ((1 << i) - 1);
            int i0 = ((p >> i) << (i + 1)) | low;
            int i1 = i0 | (1 << i);
            float x0 = bv[i0], x1 = bv[i1];
            bv[i0] = c * x0 - s * x1;
            bv[i1] = cp * (s * x0 + c * x1);
        }
        __syncthreads();
    }
    for (int idx = t; idx < HD*HD; idx += 256) {
        int i = idx >> 6, j = idx & 63;
        float acc = (i == j) ? 1.0f : 0.0f;
        #pragma unroll 8
        for (int d = 0; d < HD; d++) acc += postW[i*HD + d] * A[d][j];
        Meff[idx] = acc;
    }
    if (t < HD) {
        float acc = postb[t];
        #pragma unroll 8
        for (int d = 0; d < HD; d++) acc += postW[t*HD + d] * bv[d];
        beff[t] = acc;
    }
}

// weff[r][j] = sum_d M[i][d] * w[(h*64+d)*EMB + j], written as bf16x2 planes (pairs along j)
__global__ __launch_bounds__(256) void make_weff_bf(
    const float* __restrict__ M, const float* __restrict__ w, uint32_t* __restrict__ wp)
{
    int r = blockIdx.y;
    int jp = blockIdx.x * 256 + threadIdx.x;   // 0..511 pair index
    int h = r >> 6, i = r & 63;
    __shared__ float Mrow[HD];
    if (threadIdx.x < HD) Mrow[threadIdx.x] = M[i*HD + threadIdx.x];
    __syncthreads();
    float a0 = 0.0f, a1 = 0.0f;
    int j = jp * 2;
    #pragma unroll 8
    for (int d = 0; d < HD; d++) {
        float m = Mrow[d];
        a0 += m * w[(h*HD + d) * EMB + j];
        a1 += m * w[(h*HD + d) * EMB + j + 1];
    }
    size_t idx = (size_t)r * 512 + jp;
    pack2(a0, a1, wp + idx, wp + PLB + idx);
}

__global__ __launch_bounds__(256) void make_beff(
    const float* __restrict__ M, const float* __restrict__ beff,
    const float* __restrict__ b_in, float* __restrict__ bfull)
{
    int r = blockIdx.x * 256 + threadIdx.x;
    int h = r >> 6, i = r & 63;
    float acc = beff[i];
    #pragma unroll 8
    for (int d = 0; d < HD; d++) acc += M[i*HD + d] * b_in[h*HD + d];
    bfull[r] = acc;
}

// elementwise fp32 -> bf16x2 hi/lo planes
__global__ __launch_bounds__(256) void split2bf(
    const float* __restrict__ x, uint32_t* __restrict__ planes, uint32_t plstride, int npairs)
{
    int i = blockIdx.x * 256 + threadIdx.x;
    if (i >= npairs) return;
    float2 v = reinterpret_cast<const float2*>(x)[i];
    pack2(v.x, v.y, planes + i, planes + plstride + i);
}

// ---------------- bf16x2 tensor-core GEMM (3 products), cp.async double-buffered ----------
// C(8192x1024) = X @ W^T + bias. BM=BN=128, k-slab 16, 8 warps (2x4), warp tile 64x32.
// A, B pre-split bf16x2 planes. Per k16 per warp-tile: 3 mma.m16n8k16 (hh + lh + hl).
// mode: 0 = fp32 flat (m,n); 1 = bf16x2 planes scatter (b,h,s,d); 2 = tf32-rounded fp32 scatter.
#define GEMM_SMEM 49152   // 2 stages * (A 2 planes + B 2 planes) * 128*12 u32
__device__ __forceinline__ void gemm_stage_cp(
    const uint32_t* __restrict__ A, const uint32_t* __restrict__ B,
    uint32_t* base, int t, int m0, int n0, int ks)
{
    #pragma unroll
    for (int p = 0; p < 4; p++) {
        int c = t + p * 256;
        if (c < 512) {
            int plane = c >> 8, row = (c >> 1) & 127, half = c & 1;
            cp16(base + plane*1536 + row*12 + half*4,
                 A + (size_t)plane*PLA + (size_t)(m0+row)*512 + ks*8 + half*4);
        } else {
            int c2 = c - 512;
            int plane = c2 >> 8, row = (c2 >> 1) & 127, half = c2 & 1;
            cp16(base + 3072 + plane*1536 + row*12 + half*4,
                 B + (size_t)plane*PLB + (size_t)(n0+row)*512 + ks*8 + half*4);
        }
    }
    cp_commit();
}

__global__ __launch_bounds__(256) void gemm_bf(
    const uint32_t* __restrict__ A, const uint32_t* __restrict__ B,
    const float* __restrict__ bias, void* __restrict__ outv, int mode)
{
    extern __shared__ uint32_t smu[];
    int t = threadIdx.x;
    int lane = t & 31, w = t >> 5;
    int gid = lane >> 2, tig = lane & 3;
    int wm = w >> 2, wn = w & 3;
    int m0 = blockIdx.y * 128, n0 = blockIdx.x * 128;

    float acc[4][4][4];
    #pragma unroll
    for (int i = 0; i < 4; i++)
        #pragma unroll
        for (int j = 0; j < 4; j++)
            #pragma unroll
            for (int r = 0; r < 4; r++) acc[i][j][r] = 0.0f;

    const int NSLAB = EMB / 16;  // 64
    gemm_stage_cp(A, B, smu, t, m0, n0, 0);

    for (int s = 0; s < NSLAB; s++) {
        if (s + 1 < NSLAB) {
            gemm_stage_cp(A, B, smu + ((s+1)&1)*6144, t, m0, n0, s+1);
            cp_wait1();
        } else {
            cp_wait0();
        }
        __syncthreads();
        uint32_t* A0 = smu + (s&1)*6144;
        uint32_t* A1 = A0 + 1536;
        uint32_t* B0 = A0 + 3072;
        uint32_t* B1 = A0 + 4608;

        uint32_t af[2][4][4], bfr[2][4][2];
        #pragma unroll
        for (int mt = 0; mt < 4; mt++) {
            int mr = wm*64 + mt*16;
            af[0][mt][0] = A0[(mr+gid  )*12 + tig  ];
            af[0][mt][1] = A0[(mr+gid+8)*12 + tig  ];
            af[0][mt][2] = A0[(mr+gid  )*12 + tig+4];
            af[0][mt][3] = A0[(mr+gid+8)*12 + tig+4];
            af[1][mt][0] = A1[(mr+gid  )*12 + tig  ];
            af[1][mt][1] = A1[(mr+gid+8)*12 + tig  ];
            af[1][mt][2] = A1[(mr+gid  )*12 + tig+4];
            af[1][mt][3] = A1[(mr+gid+8)*12 + tig+4];
        }
        #pragma unroll
        for (int nt = 0; nt < 4; nt++) {
            int nc = wn*32 + nt*8;
            bfr[0][nt][0] = B0[(nc+gid)*12 + tig  ];
            bfr[0][nt][1] = B0[(nc+gid)*12 + tig+4];
            bfr[1][nt][0] = B1[(nc+gid)*12 + tig  ];
            bfr[1][nt][1] = B1[(nc+gid)*12 + tig+4];
        }
        #pragma unroll
        for (int mt = 0; mt < 4; mt++)
            #pragma unroll
            for (int nt = 0; nt < 4; nt++) {
                mma_bf16(acc[mt][nt], af[0][mt], bfr[0][nt]);
                mma_bf16(acc[mt][nt], af[1][mt], bfr[0][nt]);
                mma_bf16(acc[mt][nt], af[0][mt], bfr[1][nt]);
            }
        __syncthreads();
    }

    // epilogue
    #pragma unroll
    for (int mt = 0; mt < 4; mt++) {
        int m = m0 + wm*64 + mt*16 + gid;
        #pragma unroll
        for (int nt = 0; nt < 4; nt++) {
            int n = n0 + wn*32 + nt*8 + tig*2;
            float b0 = bias[n], b1 = bias[n+1];
            float va0 = acc[mt][nt][0] + b0, va1 = acc[mt][nt][1] + b1;
            float vb0 = acc[mt][nt][2] + b0, vb1 = acc[mt][nt][3] + b1;
            if (mode == 0) {
                float* out = (float*)outv;
                *reinterpret_cast<float2*>(&out[(size_t)m * EMB + n]) = make_float2(va0, va1);
                *reinterpret_cast<float2*>(&out[(size_t)(m+8) * EMB + n]) = make_float2(vb0, vb1);
            } else {
                int h = n >> 6;
                int bb0 = m >> 11, s0 = m & 2047;
                int m1 = m + 8;
                int bb1 = m1 >> 11, s1 = m1 & 2047;
                if (mode == 1) {
                    int dp = (n & 63) >> 1;
                    size_t i0 = ((size_t)(bb0*HEADS + h) * SEQ + s0) * 32 + dp;
                    size_t i1 = ((size_t)(bb1*HEADS + h) * SEQ + s1) * 32 + dp;
                    uint32_t* O0 = (uint32_t*)outv;
                    pack2(va0, va1, O0 + i0, O0 + PLA + i0);
                    pack2(vb0, vb1, O0 + i1, O0 + PLA + i1);
                } else { // mode 2: V tf32-rounded fp32 (b,h,s,d)
                    float* out = (float*)outv;
                    int d = n & 63;
                    size_t f0 = ((size_t)(bb0*HEADS + h) * SEQ + s0) * HD + d;
                    size_t f1 = ((size_t)(bb1*HEADS + h) * SEQ + s1) * HD + d;
                    *reinterpret_cast<float2*>(&out[f0]) =
                        make_float2(__uint_as_float(f2tf(va0)), __uint_as_float(f2tf(va1)));
                    *reinterpret_cast<float2*>(&out[f1]) =
                        make_float2(__uint_as_float(f2tf(vb0)), __uint_as_float(f2tf(vb1)));
                }
            }
        }
    }
}

// ---------------- flash attention: bf16x2 QK + tf32 PV, cp.async double-buffered ----------
// Block: 128 q-rows of one (b,h), 8 warps x 16 rows. KV tiles of 32. Register softmax.
// smem (u32 units):
//   stage s at s*4608: K0[32][36] @+0, K1 @+1152, V fp32 [32][72] @+2304
//   PS fp32 [128][36] @ 9216    total 13824 u32 = 55296 B
//   Q planes overlay [0, 9216) during prologue
#define FL_SMEM_BYTES 55296
__global__ __launch_bounds__(256) void flash_bf(
    const uint32_t* __restrict__ Qp, const uint32_t* __restrict__ Kp,
    const float* __restrict__ Vh, uint32_t* __restrict__ Op)
{
    extern __shared__ uint32_t smu[];
    float* PSf = reinterpret_cast<float*>(smu + 9216);

    int t = threadIdx.x;
    int lane = t & 31, w = t >> 5;
    int gid = lane >> 2, tig = lane & 3;
    int bh_ = blockIdx.y;
    int q0 = blockIdx.x * 128;
    size_t bhbase = (size_t)bh_ * SEQ;

    // ---- stage Q planes, extract bf16 fragments to registers ----
    #pragma unroll
    for (int p = 0; p < 8; p++) {
        int c = t + p * 256;
        int plane = c >> 10, row = (c >> 3) & 127, h16 = c & 7;
        cp16(smu + plane*4608 + row*36 + h16*4,
             Qp + (size_t)plane*PLA + (bhbase + q0 + row)*32 + h16*4);
    }
    cp_commit(); cp_wait0();
    __syncthreads();
    uint32_t qa[2][4][4];
    {
        int r0 = w * 16 + gid;
        #pragma unroll
        for (int kq = 0; kq < 4; kq++) {
            int col = kq*8 + tig;
            #pragma unroll
            for (int p = 0; p < 2; p++) {
                const uint32_t* Qb = smu + p*4608;
                qa[p][kq][0] = Qb[(r0  )*36 + col  ];
                qa[p][kq][1] = Qb[(r0+8)*36 + col  ];
                qa[p][kq][2] = Qb[(r0  )*36 + col+4];
                qa[p][kq][3] = Qb[(r0+8)*36 + col+4];
            }
        }
    }
    __syncthreads();   // Q frags in regs; smem free for K/V staging

    float o[8][4];
    #pragma unroll
    for (int i = 0; i < 8; i++)
        #pragma unroll
        for (int j = 0; j < 4; j++) o[i][j] = 0.0f;
    float m0v = -1e30f, m1v = -1e30f, l0 = 0.0f, l1 = 0.0f;
    const float SCALE = 0.125f;

    const int NT = SEQ / 32;  // 64 tiles
    // prologue: tile 0 -> stage 0
    {
        uint32_t* stg = smu;
        #pragma unroll
        for (int p = 0; p < 4; p++) {
            int c = t + p * 256;
            if (c < 512) {
                int plane = c >> 8, row = (c >> 3) & 31, h16 = c & 7;
                cp16(stg + plane*1152 + row*36 + h16*4,
                     Kp + (size_t)plane*PLA + (bhbase + row)*32 + h16*4);
            } else {
                int cv = c - 512;
                int row = cv >> 4, h16 = cv & 15;
                cp16(stg + 2304 + row*72 + h16*4,
                     Vh + (bhbase + row)*HD + h16*4);
            }
        }
        cp_commit();
    }

    for (int tt = 0; tt < NT; tt++) {
        if (tt + 1 < NT) {
            uint32_t* stg = smu + ((tt+1)&1)*4608;
            size_t kt = (size_t)(tt + 1) * 32;
            #pragma unroll
            for (int p = 0; p < 4; p++) {
                int c = t + p * 256;
                if (c < 512) {
                    int plane = c >> 8, row = (c >> 3) & 31, h16 = c & 7;
                    cp16(stg + plane*1152 + row*36 + h16*4,
                         Kp + (size_t)plane*PLA + (bhbase + kt + row)*32 + h16*4);
                } else {
                    int cv = c - 512;
                    int row = cv >> 4, h16 = cv & 15;
                    cp16(stg + 2304 + row*72 + h16*4,
                         Vh + (bhbase + kt + row)*HD + h16*4);
                }
            }
            cp_commit();
            cp_wait1();
        } else {
            cp_wait0();
        }
        __syncthreads();
        uint32_t* K0 = smu + (tt&1)*4608;
        uint32_t* K1 = K0 + 1152;
        float* Vt = reinterpret_cast<float*>(K0 + 2304);

        // S = Q @ K^T  (16 rows x 32 cols per warp), bf16x2 3-product
        float s4[4][4];
        #pragma unroll
        for (int nt = 0; nt < 4; nt++)
            #pragma unroll
            for (int r = 0; r < 4; r++) s4[nt][r] = 0.0f;
        #pragma unroll
        for (int kq = 0; kq < 4; kq++) {
            int col = kq*8 + tig;
            uint32_t kb[2][4][2];
            #pragma unroll
            for (int nt = 0; nt < 4; nt++) {
                int kr = nt*8 + gid;
                kb[0][nt][0] = K0[kr*36 + col  ];
                kb[0][nt][1] = K0[kr*36 + col+4];
                kb[1][nt][0] = K1[kr*36 + col  ];
                kb[1][nt][1] = K1[kr*36 + col+4];
            }
            #pragma unroll
            for (int nt = 0; nt < 4; nt++) {
                mma_bf16(s4[nt], qa[0][kq], kb[0][nt]);
                mma_bf16(s4[nt], qa[1][kq], kb[0][nt]);
                mma_bf16(s4[nt], qa[0][kq], kb[1][nt]);
            }
        }

        // register softmax: thread owns rows (w*16+gid) and (+8), 8 cols each
        float tm0 = -1e30f, tm1 = -1e30f;
        #pragma unroll
        for (int nt = 0; nt < 4; nt++) {
            tm0 = fmaxf(tm0, fmaxf(s4[nt][0], s4[nt][1]));
            tm1 = fmaxf(tm1, fmaxf(s4[nt][2], s4[nt][3]));
        }
        tm0 *= SCALE; tm1 *= SCALE;
        tm0 = fmaxf(tm0, __shfl_xor_sync(0xffffffffu, tm0, 1));
        tm0 = fmaxf(tm0, __shfl_xor_sync(0xffffffffu, tm0, 2));
        tm1 = fmaxf(tm1, __shfl_xor_sync(0xffffffffu, tm1, 1));
        tm1 = fmaxf(tm1, __shfl_xor_sync(0xffffffffu, tm1, 2));
        float mn0 = fmaxf(m0v, tm0), mn1 = fmaxf(m1v, tm1);
        float a0s = __expf(m0v - mn0), a1s = __expf(m1v - mn1);
        m0v = mn0; m1v = mn1;
        float rs0 = 0.0f, rs1 = 0.0f;
        int prow = w * 16 + gid;
        #pragma unroll
        for (int nt = 0; nt < 4; nt++) {
            float p0 = __expf(s4[nt][0]*SCALE - mn0);
            float p1 = __expf(s4[nt][1]*SCALE - mn0);
            float p2 = __expf(s4[nt][2]*SCALE - mn1);
            float p3 = __expf(s4[nt][3]*SCALE - mn1);
            rs0 += p0 + p1; rs1 += p2 + p3;
            int col = nt*8 + tig*2;
            PSf[(prow  )*36 + col  ] = __uint_as_float(f2tf(p0));
            PSf[(prow  )*36 + col+1] = __uint_as_float(f2tf(p1));
            PSf[(prow+8)*36 + col  ] = __uint_as_float(f2tf(p2));
            PSf[(prow+8)*36 + col+1] = __uint_as_float(f2tf(p3));
        }
        rs0 += __shfl_xor_sync(0xffffffffu, rs0, 1);
        rs0 += __shfl_xor_sync(0xffffffffu, rs0, 2);
        rs1 += __shfl_xor_sync(0xffffffffu, rs1, 1);
        rs1 += __shfl_xor_sync(0xffffffffu, rs1, 2);
        l0 = l0 * a0s + rs0;
        l1 = l1 * a1s + rs1;
        #pragma unroll
        for (int nt = 0; nt < 8; nt++) {
            o[nt][0] *= a0s; o[nt][1] *= a0s;
            o[nt][2] *= a1s; o[nt][3] *= a1s;
        }
        __syncwarp();

        // O += P @ V   (P and V tf32, 1 mma per k8 tile -> unchanged)
        #pragma unroll
        for (int kp = 0; kp < 4; kp++) {
            uint32_t af2[4];
            af2[0] = fbits(PSf[(prow  )*36 + kp*8+tig  ]);
            af2[1] = fbits(PSf[(prow+8)*36 + kp*8+tig  ]);
            af2[2] = fbits(PSf[(prow  )*36 + kp*8+tig+4]);
            af2[3] = fbits(PSf[(prow+8)*36 + kp*8+tig+4]);
            #pragma unroll
            for (int nt = 0; nt < 8; nt++) {
                uint32_t bv2[2];
                bv2[0] = fbits(Vt[(kp*8+tig  )*72 + nt*8+gid]);
                bv2[1] = fbits(Vt[(kp*8+tig+4)*72 + nt*8+gid]);
                mma_tf32(o[nt], af2, bv2);
            }
        }
        __syncthreads();   // all warps done reading this stage before it is refilled
    }

    // epilogue -> O bf16x2 planes in (b,s,e) layout
    float inv0 = 1.0f / l0, inv1 = 1.0f / l1;
    int b = bh_ >> 4, h = bh_ & 15;
    int grow = q0 + w * 16 + gid;
    #pragma unroll
    for (int nt = 0; nt < 8; nt++) {
        int colp = (h*HD + nt*8 + tig*2) >> 1;
        size_t i0 = ((size_t)(b*SEQ + grow    )) * 512 + colp;
        size_t i1 = ((size_t)(b*SEQ + grow + 8)) * 512 + colp;
        pack2(o[nt][0]*inv0, o[nt][1]*inv0, Op + i0, Op + PLA + i0);
        pack2(o[nt][2]*inv1, o[nt][3]*inv1, Op + i1, Op + PLA + i1);
    }
}

// ---------------- launch ----------------
extern "C" void kernel_launch(void* const* d_in, const int* in_sizes, int n_in,
                              void* d_out, int out_size)
{
    const float* query   = (const float*)d_in[0];
    const float* key     = (const float*)d_in[1];
    const float* value   = (const float*)d_in[2];
    const float* wq      = (const float*)d_in[3];
    const float* bq      = (const float*)d_in[4];
    const float* wk      = (const float*)d_in[5];
    const float* bk      = (const float*)d_in[6];
    const float* wv      = (const float*)d_in[7];
    const float* bv      = (const float*)d_in[8];
    const float* wo      = (const float*)d_in[9];
    const float* bo      = (const float*)d_in[10];
    const float* q_theta = (const float*)d_in[11];
    const float* q_phi   = (const float*)d_in[12];
    const float* q_preW  = (const float*)d_in[13];
    const float* q_preb  = (const float*)d_in[14];
    const float* q_postW = (const float*)d_in[15];
    const float* q_postb = (const float*)d_in[16];
    const float* k_theta = (const float*)d_in[17];
    const float* k_phi   = (const float*)d_in[18];
    const float* k_preW  = (const float*)d_in[19];
    const float* k_preb  = (const float*)d_in[20];
    const float* k_postW = (const float*)d_in[21];
    const float* k_postb = (const float*)d_in[22];

    static uint32_t *Xq = nullptr, *Xk, *Xv, *Opl, *Qp, *Kp, *Wqp, *Wkp, *Wvp, *Wop;
    static float *Vh, *Mq, *Mk, *beq, *bek, *bqf, *bkf;
    if (!Xq) {
        cudaGetSymbolAddress((void**)&Xq,  g_Xq);
        cudaGetSymbolAddress((void**)&Xk,  g_Xk);
        cudaGetSymbolAddress((void**)&Xv,  g_Xv);
        cudaGetSymbolAddress((void**)&Opl, g_Op);
        cudaGetSymbolAddress((void**)&Qp,  g_Qp);
        cudaGetSymbolAddress((void**)&Kp,  g_Kp);
        cudaGetSymbolAddress((void**)&Wqp, g_Wqp);
        cudaGetSymbolAddress((void**)&Wkp, g_Wkp);
        cudaGetSymbolAddress((void**)&Wvp, g_Wvp);
        cudaGetSymbolAddress((void**)&Wop, g_Wop);
        cudaGetSymbolAddress((void**)&Vh,  g_Vh);
        cudaGetSymbolAddress((void**)&Mq,  g_Mq);
        cudaGetSymbolAddress((void**)&Mk,  g_Mk);
        cudaGetSymbolAddress((void**)&beq, g_beq);
        cudaGetSymbolAddress((void**)&bek, g_bek);
        cudaGetSymbolAddress((void**)&bqf, g_bqf);
        cudaGetSymbolAddress((void**)&bkf, g_bkf);
        cudaFuncSetAttribute(gemm_bf,  cudaFuncAttributeMaxDynamicSharedMemorySize, GEMM_SMEM);
        cudaFuncSetAttribute(flash_bf, cudaFuncAttributeMaxDynamicSharedMemorySize, FL_SMEM_BYTES);
    }

    // 1) fold the quantum layer into effective projection weights/biases (bf16 planes)
    quantum_compose<<<1, 256>>>(q_theta, q_phi, q_preW, q_preb, q_postW, q_postb, Mq, beq);
    quantum_compose<<<1, 256>>>(k_theta, k_phi, k_preW, k_preb, k_postW, k_postb, Mk, bek);
    make_weff_bf<<<dim3(2, EMB), 256>>>(Mq, wq, Wqp);
    make_weff_bf<<<dim3(2, EMB), 256>>>(Mk, wk, Wkp);
    make_beff<<<4, 256>>>(Mq, beq, bq, bqf);
    make_beff<<<4, 256>>>(Mk, bek, bk, bkf);

    // 2) pre-split activations and static weights into bf16x2 planes
    split2bf<<<PLA/256, 256>>>(query, Xq, PLA, PLA);
    split2bf<<<PLA/256, 256>>>(key,   Xk, PLA, PLA);
    split2bf<<<PLA/256, 256>>>(value, Xv, PLA, PLA);
    split2bf<<<PLB/256, 256>>>(wv, Wvp, PLB, PLB);
    split2bf<<<PLB/256, 256>>>(wo, Wop, PLB, PLB);

    // 3) projections; Q/K -> bf16x2 planes, V -> tf32-rounded fp32
    dim3 gg(EMB / 128, NTOK / 128);
    gemm_bf<<<gg, 256, GEMM_SMEM>>>(Xq, Wqp, bqf, Qp, 1);
    gemm_bf<<<gg, 256, GEMM_SMEM>>>(Xk, Wkp, bkf, Kp, 1);
    gemm_bf<<<gg, 256, GEMM_SMEM>>>(Xv, Wvp, bv,  Vh, 2);

    // 4) attention -> bf16x2 planes (b,s,e)
    flash_bf<<<dim3(SEQ / 128, BH), 256, FL_SMEM_BYTES>>>(Qp, Kp, Vh, Opl);

    // 5) output projection -> fp32 d_out
    gemm_bf<<<gg, 256, GEMM_SMEM>>>(Opl, Wop, bo, (float*)d_out, 0);
}